// round 10
// baseline (speedup 1.0000x reference)
#include <cuda_runtime.h>
#include <cuda_bf16.h>
#include <cstdint>

#define N_NODES 90000
#define N_EDGES 540000
#define IN_F    30
#define N_GRAPH 10000

// ======================= global scratch =======================
__device__ float g_z1s[N_NODES * 128];
__device__ float g_z1t[N_NODES * 128];
__device__ float g_z2s[N_NODES * 64];
__device__ float g_z2t[N_NODES * 64];
__device__ __nv_bfloat16 g_pwh[2][4][128 * 128];   // prepared weights [branch][layer][n][k]
__device__ __nv_bfloat16 g_pwl[2][4][128 * 128];
__device__ int g_deg[N_NODES];
__device__ int g_cursor[N_NODES];
__device__ int g_rowptr[N_NODES + 1];
__device__ int g_csrsrc[N_EDGES];
__device__ int g_bsum[128];
__device__ int g_boff[128];

__device__ __forceinline__ void bf16_split(float v, __nv_bfloat16& h, __nv_bfloat16& l) {
    h = __float2bfloat16(v);
    l = __float2bfloat16(v - __bfloat162float(h));
}
__device__ __forceinline__ void split_pack(float v0, float v1, uint32_t& hi, uint32_t& lo) {
    __nv_bfloat16 h0, l0, h1, l1;
    bf16_split(v0, h0, l0);
    bf16_split(v1, h1, l1);
    __nv_bfloat162 ph; ph.x = h0; ph.y = h1;
    __nv_bfloat162 pl; pl.x = l0; pl.y = l1;
    hi = *(uint32_t*)&ph; lo = *(uint32_t*)&pl;
}

// bf16 tensor-core MMA, fp32 accumulate (family-portable, sm_80+)
__device__ __forceinline__ void mma16816(float* d, const uint32_t* a, const uint32_t* b) {
    asm volatile(
        "mma.sync.aligned.m16n8k16.row.col.f32.bf16.bf16.f32 "
        "{%0,%1,%2,%3}, {%4,%5,%6,%7}, {%8,%9}, {%0,%1,%2,%3};\n"
        : "+f"(d[0]), "+f"(d[1]), "+f"(d[2]), "+f"(d[3])
        : "r"(a[0]), "r"(a[1]), "r"(a[2]), "r"(a[3]), "r"(b[0]), "r"(b[1]));
}
#define LDSM4(r0, r1, r2, r3, addr) \
    asm volatile("ldmatrix.sync.aligned.m8n8.x4.shared.b16 {%0,%1,%2,%3}, [%4];" \
        : "=r"(r0), "=r"(r1), "=r"(r2), "=r"(r3) : "r"(addr))

__device__ __forceinline__ uint32_t smem_u32(const void* p) {
    uint32_t a;
    asm("{ .reg .u64 t; cvta.to.shared.u64 t, %1; cvt.u32.u64 %0, t; }" : "=r"(a) : "l"(p));
    return a;
}

// ======================= CSR build =======================
__global__ void zero_kernel() {
    int i = blockIdx.x * blockDim.x + threadIdx.x;
    if (i < N_NODES) { g_deg[i] = 0; g_cursor[i] = 0; }
}
__global__ void hist_kernel(const int* __restrict__ ei) {
    int e = blockIdx.x * blockDim.x + threadIdx.x;
    if (e < N_EDGES) atomicAdd(&g_deg[ei[N_EDGES + e]], 1);
}
__global__ void scan1_kernel() {
    __shared__ int sm[1024];
    int t = threadIdx.x;
    int idx = blockIdx.x * 1024 + t;
    int d = (idx < N_NODES) ? g_deg[idx] : 0;
    sm[t] = d;
    __syncthreads();
    #pragma unroll
    for (int off = 1; off < 1024; off <<= 1) {
        int v = (t >= off) ? sm[t - off] : 0;
        __syncthreads();
        sm[t] += v;
        __syncthreads();
    }
    if (idx < N_NODES) g_rowptr[idx] = sm[t] - d;
    if (t == 1023) g_bsum[blockIdx.x] = sm[1023];
}
__global__ void scan2_kernel(int nblocks) {
    __shared__ int sm[128];
    int t = threadIdx.x;
    int v = (t < nblocks) ? g_bsum[t] : 0;
    sm[t] = v;
    __syncthreads();
    #pragma unroll
    for (int off = 1; off < 128; off <<= 1) {
        int u = (t >= off) ? sm[t - off] : 0;
        __syncthreads();
        sm[t] += u;
        __syncthreads();
    }
    if (t < nblocks) g_boff[t] = sm[t] - v;
    if (t == nblocks - 1) g_rowptr[N_NODES] = sm[t];
}
__global__ void scan3_kernel() {
    int idx = blockIdx.x * 1024 + threadIdx.x;
    if (idx < N_NODES) g_rowptr[idx] += g_boff[blockIdx.x];
}
__global__ void fill_kernel(const int* __restrict__ ei) {
    int e = blockIdx.x * blockDim.x + threadIdx.x;
    if (e < N_EDGES) {
        int src = ei[e];
        int dst = ei[N_EDGES + e];
        int pos = g_rowptr[dst] + atomicAdd(&g_cursor[dst], 1);
        g_csrsrc[pos] = src;
    }
}

// ======================= weight prep, all 8 weights in ONE launch =======================
__global__ void prep_all_kernel(
    const float* w0, const float* w1, const float* w2, const float* w3,
    const float* w4, const float* w5, const float* w6, const float* w7)
{
    const int KREAL[4] = { IN_F, 128, 128, 128 };
    const int KSM[4]   = { 32, 128, 128, 128 };
    const int NOUT[4]  = { 128, 128, 128, 64 };
    const float* Ws[8] = { w0, w1, w2, w3, w4, w5, w6, w7 };
    int y = blockIdx.y;
    int br = y >> 2, li = y & 3;
    int n = blockIdx.x;
    int k = threadIdx.x;
    if (n >= NOUT[li] || k >= KSM[li]) return;
    const float* W = Ws[y];
    float v = (k < KREAL[li]) ? W[k * NOUT[li] + n] : 0.f;
    __nv_bfloat16 h, l;
    bf16_split(v, h, l);
    g_pwh[br][li][n * KSM[li] + k] = h;
    g_pwl[br][li][n * KSM[li] + k] = l;
}

// ======================= fused GIN layer: gather-agg + 2-layer MLP =======================
// load stage: A[r] = input[gr] + sum_{src->gr} input[src]   (fp32, then split hi/lo to smem)
// pass1: H = relu(A[64 x K1] @ W1^T + b1) -> smem (bf16 hi/lo), 128 wide
// pass2: Z = H[64 x 128] @ W2^T + b2 (NOUT2 = NT2*32) -> global fp32
// split precision: D = Ah*Bh + Ah*Bl + Al*Bh. Both branches via blockIdx.y.
// 8 warps: warpM = wid&1 (2 x 32 rows), warpN = wid>>1 (4 x N/4 cols)
template<int K1, int NT2>
__global__ __launch_bounds__(256, 2) void mlp_kernel(
    const float* __restrict__ X,
    const float* __restrict__ B1a, const float* __restrict__ B1b,
    const float* __restrict__ B2a, const float* __restrict__ B2b)
{
    constexpr int PK1 = K1 + 8;
    constexpr int PK2 = 136;
    constexpr int ATILE = 64 * PK2;       // halfs per A buffer
    constexpr int WTILE = 128 * PK2;      // halfs per W buffer
    constexpr int NOUT2 = NT2 * 32;       // 128 or 64
    extern __shared__ char smraw[];
    __nv_bfloat16* AH = (__nv_bfloat16*)smraw;
    __nv_bfloat16* AL = AH + ATILE;
    __nv_bfloat16* WH = AL + ATILE;
    __nv_bfloat16* WL = WH + WTILE;

    int tid = threadIdx.x, lane = tid & 31, wid = tid >> 5;
    int warpM = wid & 1, warpN = wid >> 1;
    int by = blockIdx.y;
    int row0 = blockIdx.x * 64;
    int lg = lane >> 2;
    int lt = lane & 3;

    int l1 = (K1 == 32) ? 0 : 2;
    const __nv_bfloat16* W1h = g_pwh[by][l1];
    const __nv_bfloat16* W1l = g_pwl[by][l1];
    const __nv_bfloat16* W2h = g_pwh[by][l1 + 1];
    const __nv_bfloat16* W2l = g_pwl[by][l1 + 1];
    const float* B1 = by ? B1b : B1a;
    const float* B2 = by ? B2b : B2a;

    // ---- load W1 [128 x K1] into smem (pitch PK1) — streaming, issue first ----
    {
        constexpr int CPR = PK1 / 8;
        for (int i = tid; i < 128 * CPR; i += 256) {
            int r = i / CPR, c = i % CPR, col = c * 8;
            float4 zf = make_float4(0.f, 0.f, 0.f, 0.f);
            float4 wh = zf, wl = zf;
            if (col < K1) {
                wh = *(const float4*)(W1h + r * K1 + col);
                wl = *(const float4*)(W1l + r * K1 + col);
            }
            *(float4*)(WH + r * PK1 + col) = wh;
            *(float4*)(WL + r * PK1 + col) = wl;
        }
    }

    // ---- gather-aggregate A tile: 8 warps x 8 rows, lane = feature slot ----
    {
        int rbase = wid * 8;
        for (int rr = 0; rr < 8; rr++) {
            int r = rbase + rr;
            int gr = row0 + r;
            if (K1 == 32) {
                // input x [N, 30], lane = feature (lanes 30/31 zero)
                float acc = 0.f;
                if (gr < N_NODES) {
                    if (lane < IN_F) acc = X[gr * IN_F + lane];
                    int s0 = g_rowptr[gr], s1 = g_rowptr[gr + 1];
                    for (int e = s0; e < s1; e++) {
                        int s = g_csrsrc[e];
                        if (lane < IN_F) acc += X[s * IN_F + lane];
                    }
                }
                __nv_bfloat16 h, l;
                bf16_split(acc, h, l);
                AH[r * PK1 + lane] = h;
                AL[r * PK1 + lane] = l;
            } else {
                // input z1 [N, 128] fp32, lane = float4 slot
                const float4* Z = (const float4*)(by ? g_z1t : g_z1s);
                float4 acc = make_float4(0.f, 0.f, 0.f, 0.f);
                if (gr < N_NODES) {
                    acc = Z[(size_t)gr * 32 + lane];
                    int s0 = g_rowptr[gr], s1 = g_rowptr[gr + 1];
                    for (int e = s0; e < s1; e++) {
                        int s = g_csrsrc[e];
                        float4 v = Z[(size_t)s * 32 + lane];
                        acc.x += v.x; acc.y += v.y; acc.z += v.z; acc.w += v.w;
                    }
                }
                uint32_t h01, l01, h23, l23;
                split_pack(acc.x, acc.y, h01, l01);
                split_pack(acc.z, acc.w, h23, l23);
                uint32_t* oh = (uint32_t*)(AH + r * PK1 + lane * 4);
                uint32_t* ol = (uint32_t*)(AL + r * PK1 + lane * 4);
                oh[0] = h01; oh[1] = h23;
                ol[0] = l01; ol[1] = l23;
            }
        }
    }
    __syncthreads();

    // ldmatrix lane->addr components (same mapping as verified R3/R5/R8 kernels)
    int a_row = lane & 15;
    int a_col = (lane >> 4) * 8;
    int b_row = (lane & 7) + ((lane >> 4) & 1) * 8;
    int b_col = ((lane >> 3) & 1) * 8;

    uint32_t uAH = smem_u32(AH), uAL = smem_u32(AL);
    uint32_t uWH = smem_u32(WH), uWL = smem_u32(WL);

    // ---- pass 1: 64 x 128, warp tile 32 x 32 ----
    float acc[2][4][4];
    #pragma unroll
    for (int tm = 0; tm < 2; tm++)
        #pragma unroll
        for (int tn = 0; tn < 4; tn++)
            #pragma unroll
            for (int q = 0; q < 4; q++) acc[tm][tn][q] = 0.f;

    {
        uint32_t aBH[2], aBL[2], bBH[2], bBL[2];
        #pragma unroll
        for (int tm = 0; tm < 2; tm++) {
            int R = warpM * 32 + tm * 16;
            aBH[tm] = uAH + ((R + a_row) * PK1 + a_col) * 2;
            aBL[tm] = uAL + ((R + a_row) * PK1 + a_col) * 2;
        }
        #pragma unroll
        for (int pp = 0; pp < 2; pp++) {
            int N0 = warpN * 32 + pp * 16;
            bBH[pp] = uWH + ((N0 + b_row) * PK1 + b_col) * 2;
            bBL[pp] = uWL + ((N0 + b_row) * PK1 + b_col) * 2;
        }
        #pragma unroll
        for (int ks = 0; ks < K1 / 16; ks++) {
            uint32_t ah[2][4], al[2][4];
            #pragma unroll
            for (int tm = 0; tm < 2; tm++) {
                LDSM4(ah[tm][0], ah[tm][1], ah[tm][2], ah[tm][3], aBH[tm] + ks * 32);
                LDSM4(al[tm][0], al[tm][1], al[tm][2], al[tm][3], aBL[tm] + ks * 32);
            }
            #pragma unroll
            for (int pp = 0; pp < 2; pp++) {
                uint32_t bh[4], bl[4];
                LDSM4(bh[0], bh[1], bh[2], bh[3], bBH[pp] + ks * 32);
                LDSM4(bl[0], bl[1], bl[2], bl[3], bBL[pp] + ks * 32);
                #pragma unroll
                for (int hf = 0; hf < 2; hf++) {
                    int tn = pp * 2 + hf;
                    #pragma unroll
                    for (int tm = 0; tm < 2; tm++) {
                        mma16816(acc[tm][tn], ah[tm], bh + 2 * hf);
                        mma16816(acc[tm][tn], ah[tm], bl + 2 * hf);
                        mma16816(acc[tm][tn], al[tm], bh + 2 * hf);
                    }
                }
            }
        }
    }
    __syncthreads();   // done reading A/W1

    // ---- stage H = relu(acc + b1) -> A region (split hi/lo), pitch PK2 ----
    #pragma unroll
    for (int tm = 0; tm < 2; tm++) {
        int m = warpM * 32 + tm * 16 + lg;
        #pragma unroll
        for (int tn = 0; tn < 4; tn++) {
            int n = warpN * 32 + tn * 8 + lt * 2;
            float2 bv = *(const float2*)(B1 + n);
            float v0 = fmaxf(acc[tm][tn][0] + bv.x, 0.f);
            float v1 = fmaxf(acc[tm][tn][1] + bv.y, 0.f);
            float v2 = fmaxf(acc[tm][tn][2] + bv.x, 0.f);
            float v3 = fmaxf(acc[tm][tn][3] + bv.y, 0.f);
            uint32_t hi, lo;
            split_pack(v0, v1, hi, lo);
            *(uint32_t*)(AH + m * PK2 + n) = hi;
            *(uint32_t*)(AL + m * PK2 + n) = lo;
            split_pack(v2, v3, hi, lo);
            *(uint32_t*)(AH + (m + 8) * PK2 + n) = hi;
            *(uint32_t*)(AL + (m + 8) * PK2 + n) = lo;
        }
    }
    // ---- load W2 (NOUT2 rows x 128) into W region (pitch PK2) ----
    for (int i = tid; i < NOUT2 * 17; i += 256) {
        int r = i / 17, c = i % 17, col = c * 8;
        float4 wh = make_float4(0.f, 0.f, 0.f, 0.f), wl = wh;
        if (col < 128) {
            wh = *(const float4*)(W2h + r * 128 + col);
            wl = *(const float4*)(W2l + r * 128 + col);
        }
        *(float4*)(WH + r * PK2 + col) = wh;
        *(float4*)(WL + r * PK2 + col) = wl;
    }
    __syncthreads();

    // ---- pass 2: 64 x NOUT2, K = 128, warp tile 32 x NOUT2/4 ----
    float acc2[2][NT2][4];
    #pragma unroll
    for (int tm = 0; tm < 2; tm++)
        #pragma unroll
        for (int tn = 0; tn < NT2; tn++)
            #pragma unroll
            for (int q = 0; q < 4; q++) acc2[tm][tn][q] = 0.f;

    {
        uint32_t aBH[2], aBL[2], bBH[NT2 / 2], bBL[NT2 / 2];
        #pragma unroll
        for (int tm = 0; tm < 2; tm++) {
            int R = warpM * 32 + tm * 16;
            aBH[tm] = uAH + ((R + a_row) * PK2 + a_col) * 2;
            aBL[tm] = uAL + ((R + a_row) * PK2 + a_col) * 2;
        }
        #pragma unroll
        for (int pp = 0; pp < NT2 / 2; pp++) {
            int N0 = warpN * (NOUT2 / 4) + pp * 16;
            bBH[pp] = uWH + ((N0 + b_row) * PK2 + b_col) * 2;
            bBL[pp] = uWL + ((N0 + b_row) * PK2 + b_col) * 2;
        }
        #pragma unroll
        for (int ks = 0; ks < 8; ks++) {
            uint32_t ah[2][4], al[2][4];
            #pragma unroll
            for (int tm = 0; tm < 2; tm++) {
                LDSM4(ah[tm][0], ah[tm][1], ah[tm][2], ah[tm][3], aBH[tm] + ks * 32);
                LDSM4(al[tm][0], al[tm][1], al[tm][2], al[tm][3], aBL[tm] + ks * 32);
            }
            #pragma unroll
            for (int pp = 0; pp < NT2 / 2; pp++) {
                uint32_t bh[4], bl[4];
                LDSM4(bh[0], bh[1], bh[2], bh[3], bBH[pp] + ks * 32);
                LDSM4(bl[0], bl[1], bl[2], bl[3], bBL[pp] + ks * 32);
                #pragma unroll
                for (int hf = 0; hf < 2; hf++) {
                    int tn = pp * 2 + hf;
                    #pragma unroll
                    for (int tm = 0; tm < 2; tm++) {
                        mma16816(acc2[tm][tn], ah[tm], bh + 2 * hf);
                        mma16816(acc2[tm][tn], ah[tm], bl + 2 * hf);
                        mma16816(acc2[tm][tn], al[tm], bh + 2 * hf);
                    }
                }
            }
        }
    }

    // ---- epilogue: Z + b2 -> global fp32 ----
    float* outF = (K1 == 32) ? (by ? g_z1t : g_z1s) : (by ? g_z2t : g_z2s);
    #pragma unroll
    for (int tm = 0; tm < 2; tm++) {
        int m = warpM * 32 + tm * 16 + lg;
        #pragma unroll
        for (int tn = 0; tn < NT2; tn++) {
            int n = warpN * (NOUT2 / 4) + tn * 8 + lt * 2;
            float2 bv = *(const float2*)(B2 + n);
            int g0 = row0 + m;
            if (g0 < N_NODES) {
                float2 o; o.x = acc2[tm][tn][0] + bv.x; o.y = acc2[tm][tn][1] + bv.y;
                *(float2*)(outF + (size_t)g0 * NOUT2 + n) = o;
            }
            int g1 = row0 + m + 8;
            if (g1 < N_NODES) {
                float2 o; o.x = acc2[tm][tn][2] + bv.x; o.y = acc2[tm][tn][3] + bv.y;
                *(float2*)(outF + (size_t)g1 * NOUT2 + n) = o;
            }
        }
    }
}

// ======================= per-graph 9x9 gram =======================
__global__ void final_kernel(float* __restrict__ out) {
    __shared__ float zs[9 * 64];
    __shared__ float zt[9 * 64];
    int g = blockIdx.x;
    const float4* ps = (const float4*)(g_z2s + (size_t)g * 9 * 64);
    const float4* pt = (const float4*)(g_z2t + (size_t)g * 9 * 64);
    int tid = threadIdx.x;
    for (int i = tid; i < 144; i += 128) {
        ((float4*)zs)[i] = ps[i];
        ((float4*)zt)[i] = pt[i];
    }
    __syncthreads();
    if (tid < 81) {
        int i = tid / 9, j = tid % 9;
        float acc = 0.f;
        #pragma unroll
        for (int k = 0; k < 64; k++) acc += zs[i * 64 + k] * zt[j * 64 + k];
        out[(g * 9 + i) * 9 + j] = acc;
    }
}

// ======================= launch =======================
extern "C" void kernel_launch(void* const* d_in, const int* in_sizes, int n_in,
                              void* d_out, int out_size) {
    const float* x  = (const float*)d_in[0];
    const int*   ei = (const int*)d_in[1];
    const float* B[2][4] = {
        { (const float*)d_in[3],  (const float*)d_in[5],  (const float*)d_in[7],  (const float*)d_in[9]  },
        { (const float*)d_in[11], (const float*)d_in[13], (const float*)d_in[15], (const float*)d_in[17] }
    };
    float* out = (float*)d_out;

    const int SMEM = (2 * 64 * 136 + 2 * 128 * 136) * 2;   // 104448 bytes -> 2 CTA/SM
    cudaFuncSetAttribute(mlp_kernel<32, 4>,  cudaFuncAttributeMaxDynamicSharedMemorySize, SMEM);
    cudaFuncSetAttribute(mlp_kernel<128, 2>, cudaFuncAttributeMaxDynamicSharedMemorySize, SMEM);

    const int GEMM_BLOCKS = (N_NODES + 63) / 64;         // 1407
    const int SCAN_BLOCKS = (N_NODES + 1023) / 1024;     // 88

    // CSR build
    zero_kernel<<<(N_NODES + 255) / 256, 256>>>();
    hist_kernel<<<(N_EDGES + 255) / 256, 256>>>(ei);
    scan1_kernel<<<SCAN_BLOCKS, 1024>>>();
    scan2_kernel<<<1, 128>>>(SCAN_BLOCKS);
    scan3_kernel<<<SCAN_BLOCKS, 1024>>>();
    fill_kernel<<<(N_EDGES + 255) / 256, 256>>>(ei);

    // weight prep (single launch, pointers via kernel args -> capture-safe)
    prep_all_kernel<<<dim3(128, 8), 128>>>(
        (const float*)d_in[2],  (const float*)d_in[4],  (const float*)d_in[6],  (const float*)d_in[8],
        (const float*)d_in[10], (const float*)d_in[12], (const float*)d_in[14], (const float*)d_in[16]);

    // GIN layer 1 (gather + fused MLP), both branches in one launch
    mlp_kernel<32, 4><<<dim3(GEMM_BLOCKS, 2), 256, SMEM>>>(x, B[0][0], B[1][0], B[0][1], B[1][1]);

    // GIN layer 2 (gather + fused MLP), both branches in one launch
    mlp_kernel<128, 2><<<dim3(GEMM_BLOCKS, 2), 256, SMEM>>>(nullptr, B[0][2], B[1][2], B[0][3], B[1][3]);

    final_kernel<<<N_GRAPH, 128>>>(out);
}

// round 11
// speedup vs baseline: 1.3494x; 1.3494x over previous
#include <cuda_runtime.h>
#include <cuda_bf16.h>
#include <cstdint>

#define N_NODES 90000
#define N_EDGES 540000
#define IN_F    30
#define N_GRAPH 10000

// ======================= global scratch =======================
__device__ __nv_bfloat16 g_agg0_h[N_NODES * 32];
__device__ __nv_bfloat16 g_agg0_l[N_NODES * 32];
__device__ __nv_bfloat16 g_agg1s_h[N_NODES * 128];
__device__ __nv_bfloat16 g_agg1s_l[N_NODES * 128];
__device__ __nv_bfloat16 g_agg1t_h[N_NODES * 128];
__device__ __nv_bfloat16 g_agg1t_l[N_NODES * 128];
__device__ float g_z1s[N_NODES * 128];
__device__ float g_z1t[N_NODES * 128];
__device__ float g_z2s[N_NODES * 64];
__device__ float g_z2t[N_NODES * 64];
__device__ __nv_bfloat16 g_pwh[2][4][128 * 128];   // prepared weights [branch][layer][n][k]
__device__ __nv_bfloat16 g_pwl[2][4][128 * 128];
__device__ int g_deg[N_NODES];
__device__ int g_cursor[N_NODES];
__device__ int g_rowptr[N_NODES + 1];
__device__ int g_csrsrc[N_EDGES];
__device__ int g_bsum[128];
__device__ int g_boff[128];

__device__ __forceinline__ void bf16_split(float v, __nv_bfloat16& h, __nv_bfloat16& l) {
    h = __float2bfloat16(v);
    l = __float2bfloat16(v - __bfloat162float(h));
}
__device__ __forceinline__ void split_pack(float v0, float v1, uint32_t& hi, uint32_t& lo) {
    __nv_bfloat16 h0, l0, h1, l1;
    bf16_split(v0, h0, l0);
    bf16_split(v1, h1, l1);
    __nv_bfloat162 ph; ph.x = h0; ph.y = h1;
    __nv_bfloat162 pl; pl.x = l0; pl.y = l1;
    hi = *(uint32_t*)&ph; lo = *(uint32_t*)&pl;
}

// bf16 tensor-core MMA, fp32 accumulate (family-portable, sm_80+)
__device__ __forceinline__ void mma16816(float* d, const uint32_t* a, const uint32_t* b) {
    asm volatile(
        "mma.sync.aligned.m16n8k16.row.col.f32.bf16.bf16.f32 "
        "{%0,%1,%2,%3}, {%4,%5,%6,%7}, {%8,%9}, {%0,%1,%2,%3};\n"
        : "+f"(d[0]), "+f"(d[1]), "+f"(d[2]), "+f"(d[3])
        : "r"(a[0]), "r"(a[1]), "r"(a[2]), "r"(a[3]), "r"(b[0]), "r"(b[1]));
}
#define LDSM4(r0, r1, r2, r3, addr) \
    asm volatile("ldmatrix.sync.aligned.m8n8.x4.shared.b16 {%0,%1,%2,%3}, [%4];" \
        : "=r"(r0), "=r"(r1), "=r"(r2), "=r"(r3) : "r"(addr))

__device__ __forceinline__ uint32_t smem_u32(const void* p) {
    uint32_t a;
    asm("{ .reg .u64 t; cvta.to.shared.u64 t, %1; cvt.u32.u64 %0, t; }" : "=r"(a) : "l"(p));
    return a;
}

// ======================= CSR build =======================
__global__ void zero_kernel() {
    int i = blockIdx.x * blockDim.x + threadIdx.x;
    if (i < N_NODES) { g_deg[i] = 0; g_cursor[i] = 0; }
}
__global__ void hist_kernel(const int* __restrict__ ei) {
    int e = blockIdx.x * blockDim.x + threadIdx.x;
    if (e < N_EDGES) atomicAdd(&g_deg[ei[N_EDGES + e]], 1);
}
__global__ void scan1_kernel() {
    __shared__ int sm[1024];
    int t = threadIdx.x;
    int idx = blockIdx.x * 1024 + t;
    int d = (idx < N_NODES) ? g_deg[idx] : 0;
    sm[t] = d;
    __syncthreads();
    #pragma unroll
    for (int off = 1; off < 1024; off <<= 1) {
        int v = (t >= off) ? sm[t - off] : 0;
        __syncthreads();
        sm[t] += v;
        __syncthreads();
    }
    if (idx < N_NODES) g_rowptr[idx] = sm[t] - d;
    if (t == 1023) g_bsum[blockIdx.x] = sm[1023];
}
__global__ void scan2_kernel(int nblocks) {
    __shared__ int sm[128];
    int t = threadIdx.x;
    int v = (t < nblocks) ? g_bsum[t] : 0;
    sm[t] = v;
    __syncthreads();
    #pragma unroll
    for (int off = 1; off < 128; off <<= 1) {
        int u = (t >= off) ? sm[t - off] : 0;
        __syncthreads();
        sm[t] += u;
        __syncthreads();
    }
    if (t < nblocks) g_boff[t] = sm[t] - v;
    if (t == nblocks - 1) g_rowptr[N_NODES] = sm[t];
}
__global__ void scan3_kernel() {
    int idx = blockIdx.x * 1024 + threadIdx.x;
    if (idx < N_NODES) g_rowptr[idx] += g_boff[blockIdx.x];
}
__global__ void fill_kernel(const int* __restrict__ ei) {
    int e = blockIdx.x * blockDim.x + threadIdx.x;
    if (e < N_EDGES) {
        int src = ei[e];
        int dst = ei[N_EDGES + e];
        int pos = g_rowptr[dst] + atomicAdd(&g_cursor[dst], 1);
        g_csrsrc[pos] = src;
    }
}

// ======================= weight prep, all 8 weights in ONE launch =======================
__global__ void prep_all_kernel(
    const float* w0, const float* w1, const float* w2, const float* w3,
    const float* w4, const float* w5, const float* w6, const float* w7)
{
    const int KREAL[4] = { IN_F, 128, 128, 128 };
    const int KSM[4]   = { 32, 128, 128, 128 };
    const int NOUT[4]  = { 128, 128, 128, 64 };
    const float* Ws[8] = { w0, w1, w2, w3, w4, w5, w6, w7 };
    int y = blockIdx.y;
    int br = y >> 2, li = y & 3;
    int n = blockIdx.x;
    int k = threadIdx.x;
    if (n >= NOUT[li] || k >= KSM[li]) return;
    const float* W = Ws[y];
    float v = (k < KREAL[li]) ? W[k * NOUT[li] + n] : 0.f;
    __nv_bfloat16 h, l;
    bf16_split(v, h, l);
    g_pwh[br][li][n * KSM[li] + k] = h;
    g_pwl[br][li][n * KSM[li] + k] = l;
}

// ======================= layer-1 aggregation -> bf16 hi/lo, K padded to 32
__global__ void agg0_kernel(const float* __restrict__ x) {
    int w = (blockIdx.x * blockDim.x + threadIdx.x) >> 5;
    int lane = threadIdx.x & 31;
    if (w >= N_NODES) return;
    float acc = (lane < IN_F) ? x[w * IN_F + lane] : 0.f;
    int s0 = g_rowptr[w], s1 = g_rowptr[w + 1];
    for (int e = s0; e < s1; e++) {
        int s = g_csrsrc[e];
        if (lane < IN_F) acc += x[s * IN_F + lane];
    }
    __nv_bfloat16 h, l;
    bf16_split(acc, h, l);
    g_agg0_h[w * 32 + lane] = h;
    g_agg0_l[w * 32 + lane] = l;
}

// ======================= layer-2 aggregation, BOTH branches in one pass =======================
__global__ void agg1_kernel() {
    const float4* zs = (const float4*)g_z1s;
    const float4* zt = (const float4*)g_z1t;
    int w = (blockIdx.x * blockDim.x + threadIdx.x) >> 5;
    int lane = threadIdx.x & 31;
    if (w >= N_NODES) return;
    float4 as = zs[(size_t)w * 32 + lane];
    float4 at = zt[(size_t)w * 32 + lane];
    int s0 = g_rowptr[w], s1 = g_rowptr[w + 1];
    for (int e = s0; e < s1; e++) {
        int s = g_csrsrc[e];
        float4 vs = zs[(size_t)s * 32 + lane];
        float4 vt = zt[(size_t)s * 32 + lane];
        as.x += vs.x; as.y += vs.y; as.z += vs.z; as.w += vs.w;
        at.x += vt.x; at.y += vt.y; at.z += vt.z; at.w += vt.w;
    }
    uint32_t h01, l01, h23, l23;
    split_pack(as.x, as.y, h01, l01);
    split_pack(as.z, as.w, h23, l23);
    uint32_t* oh = (uint32_t*)(g_agg1s_h + (size_t)w * 128 + lane * 4);
    uint32_t* ol = (uint32_t*)(g_agg1s_l + (size_t)w * 128 + lane * 4);
    oh[0] = h01; oh[1] = h23;
    ol[0] = l01; ol[1] = l23;
    split_pack(at.x, at.y, h01, l01);
    split_pack(at.z, at.w, h23, l23);
    oh = (uint32_t*)(g_agg1t_h + (size_t)w * 128 + lane * 4);
    ol = (uint32_t*)(g_agg1t_l + (size_t)w * 128 + lane * 4);
    oh[0] = h01; oh[1] = h23;
    ol[0] = l01; ol[1] = l23;
}

// ======================= W chunk loader: 64-col chunk, XOR-swizzled, pitch 64 halfs
__device__ __forceinline__ void load_w_chunk(
    __nv_bfloat16* WH, __nv_bfloat16* WL,
    const __nv_bfloat16* __restrict__ Wh, const __nv_bfloat16* __restrict__ Wl,
    int rows, int KS, int kk, int tid)
{
    for (int i = tid; i < rows * 8; i += 256) {
        int r = i >> 3, g = i & 7;
        int col = kk * 64 + g * 8;
        float4 vh = make_float4(0.f, 0.f, 0.f, 0.f), vl = vh;
        if (col < KS) {
            vh = *(const float4*)(Wh + r * KS + col);
            vl = *(const float4*)(Wl + r * KS + col);
        }
        int dst = r * 64 + ((g ^ (r & 7)) << 3);
        *(float4*)(WH + dst) = vh;
        *(float4*)(WL + dst) = vl;
    }
}

// ======================= fused 2-layer MLP, M-tile 64, 3 CTA/SM =======================
// smem: A region 64x128 halfs (XOR-swizzled, pitch 128) x2 (hi/lo)
//       W region 128x64 halfs (one K=64 chunk, swizzled, pitch 64) x2 (hi/lo)  => 64 KB total
// pass1: H = relu(A[64 x K1] @ W1^T + b1) -> A region (bf16 hi/lo)
// pass2: Z = H[64 x 128] @ W2^T + b2 (NOUT2 = NT2*32) -> global fp32
// split precision: D = Ah*Bh + Ah*Bl + Al*Bh (identical order to R8 -> identical numerics)
template<int K1, int NT2>
__global__ __launch_bounds__(256, 3) void mlp_kernel(
    const float* __restrict__ B1a, const float* __restrict__ B1b,
    const float* __restrict__ B2a, const float* __restrict__ B2b)
{
    constexpr int NOUT2 = NT2 * 32;       // 128 or 64
    constexpr int GA = K1 / 8;            // A granules per row (4 or 16)
    constexpr int KCH1 = (K1 + 63) / 64;  // pass1 W chunks (1 or 2)
    constexpr int KS1 = K1 / 16;          // pass1 total ksteps (2 or 8)
    extern __shared__ char smraw[];
    __nv_bfloat16* AH = (__nv_bfloat16*)smraw;       // 8192 halfs
    __nv_bfloat16* AL = AH + 64 * 128;
    __nv_bfloat16* WH = AL + 64 * 128;               // 8192 halfs
    __nv_bfloat16* WL = WH + 128 * 64;

    int tid = threadIdx.x, lane = tid & 31, wid = tid >> 5;
    int warpM = wid & 1, warpN = wid >> 1;
    int by = blockIdx.y;
    int row0 = blockIdx.x * 64;
    int lg = lane >> 2, lt = lane & 3;

    int l1 = (K1 == 32) ? 0 : 2;
    const __nv_bfloat16* Agh = (K1 == 32) ? g_agg0_h : (by ? g_agg1t_h : g_agg1s_h);
    const __nv_bfloat16* Agl = (K1 == 32) ? g_agg0_l : (by ? g_agg1t_l : g_agg1s_l);
    const __nv_bfloat16* W1h = g_pwh[by][l1];
    const __nv_bfloat16* W1l = g_pwl[by][l1];
    const __nv_bfloat16* W2h = g_pwh[by][l1 + 1];
    const __nv_bfloat16* W2l = g_pwl[by][l1 + 1];
    const float* B1 = by ? B1b : B1a;
    const float* B2 = by ? B2b : B2a;

    // ---- A tile load: rows 64, GA granules, XOR swizzle, pitch 128 halfs ----
    for (int i = tid; i < 64 * GA; i += 256) {
        int r = i / GA, g = i % GA;
        int col = g * 8;
        int gr = row0 + r;
        float4 vh = make_float4(0.f, 0.f, 0.f, 0.f), vl = vh;
        if (gr < N_NODES) {
            vh = *(const float4*)(Agh + (size_t)gr * K1 + col);
            vl = *(const float4*)(Agl + (size_t)gr * K1 + col);
        }
        int dst = r * 128 + ((g ^ (r & 7)) << 3);
        *(float4*)(AH + dst) = vh;
        *(float4*)(AL + dst) = vl;
    }
    // ---- W1 chunk 0 ----
    load_w_chunk(WH, WL, W1h, W1l, 128, K1, 0, tid);
    __syncthreads();

    // ldmatrix lane->addr components (same (row, granule) mapping as verified R8)
    int a_row = lane & 15;
    int xA = lane & 7;              // (R + a_row) & 7
    int g0A = lane >> 4;            // 0/1
    int b_row = (lane & 7) + ((lane >> 4) & 1) * 8;
    int xW = b_row & 7;
    int g0W = (lane >> 3) & 1;

    uint32_t uAH = smem_u32(AH), uAL = smem_u32(AL);
    uint32_t uWH = smem_u32(WH), uWL = smem_u32(WL);

    uint32_t aRB_H[2], aRB_L[2];    // A row base addresses (bytes), pitch 256 B
    #pragma unroll
    for (int tm = 0; tm < 2; tm++) {
        int R = warpM * 32 + tm * 16;
        aRB_H[tm] = uAH + (R + a_row) * 256;
        aRB_L[tm] = uAL + (R + a_row) * 256;
    }

    // ---- pass 1: 64 x 128, warp tile 32 x 32, W streamed in K-chunks ----
    float acc[2][4][4];
    #pragma unroll
    for (int tm = 0; tm < 2; tm++)
        #pragma unroll
        for (int tn = 0; tn < 4; tn++)
            #pragma unroll
            for (int q = 0; q < 4; q++) acc[tm][tn][q] = 0.f;

    {
        uint32_t wRB_H[2], wRB_L[2];   // pitch 128 B
        #pragma unroll
        for (int pp = 0; pp < 2; pp++) {
            int N0 = warpN * 32 + pp * 16;
            wRB_H[pp] = uWH + (N0 + b_row) * 128;
            wRB_L[pp] = uWL + (N0 + b_row) * 128;
        }
        constexpr int NKS = (KCH1 == 1) ? KS1 : 4;   // ksteps per chunk
        #pragma unroll
        for (int kk = 0; kk < KCH1; kk++) {
            if (kk > 0) {
                __syncthreads();
                load_w_chunk(WH, WL, W1h, W1l, 128, K1, kk, tid);
                __syncthreads();
            }
            #pragma unroll
            for (int ks = 0; ks < NKS; ks++) {
                int gs = kk * 4 + ks;
                uint32_t ao = (uint32_t)(((gs * 2 + g0A) ^ xA) << 4);
                uint32_t wo = (uint32_t)(((ks * 2 + g0W) ^ xW) << 4);
                uint32_t ah[2][4], al[2][4];
                #pragma unroll
                for (int tm = 0; tm < 2; tm++) {
                    LDSM4(ah[tm][0], ah[tm][1], ah[tm][2], ah[tm][3], aRB_H[tm] + ao);
                    LDSM4(al[tm][0], al[tm][1], al[tm][2], al[tm][3], aRB_L[tm] + ao);
                }
                #pragma unroll
                for (int pp = 0; pp < 2; pp++) {
                    uint32_t bh[4], bl[4];
                    LDSM4(bh[0], bh[1], bh[2], bh[3], wRB_H[pp] + wo);
                    LDSM4(bl[0], bl[1], bl[2], bl[3], wRB_L[pp] + wo);
                    #pragma unroll
                    for (int hf = 0; hf < 2; hf++) {
                        int tn = pp * 2 + hf;
                        #pragma unroll
                        for (int tm = 0; tm < 2; tm++) {
                            mma16816(acc[tm][tn], ah[tm], bh + 2 * hf);
                            mma16816(acc[tm][tn], ah[tm], bl + 2 * hf);
                            mma16816(acc[tm][tn], al[tm], bh + 2 * hf);
                        }
                    }
                }
            }
        }
    }
    __syncthreads();   // pass1 reads of A and W complete

    // ---- stage H = relu(acc + b1) -> A region (swizzled, pitch 128 halfs) ----
    #pragma unroll
    for (int tm = 0; tm < 2; tm++) {
        int m = warpM * 32 + tm * 16 + lg;
        #pragma unroll
        for (int tn = 0; tn < 4; tn++) {
            int n = warpN * 32 + tn * 8 + lt * 2;
            float2 bv = *(const float2*)(B1 + n);
            float v0 = fmaxf(acc[tm][tn][0] + bv.x, 0.f);
            float v1 = fmaxf(acc[tm][tn][1] + bv.y, 0.f);
            float v2 = fmaxf(acc[tm][tn][2] + bv.x, 0.f);
            float v3 = fmaxf(acc[tm][tn][3] + bv.y, 0.f);
            uint32_t hi, lo;
            int off0 = m * 128 + (((n >> 3) ^ (m & 7)) << 3) + (n & 7);
            split_pack(v0, v1, hi, lo);
            *(uint32_t*)(AH + off0) = hi;
            *(uint32_t*)(AL + off0) = lo;
            int off1 = (m + 8) * 128 + (((n >> 3) ^ (m & 7)) << 3) + (n & 7);  // (m+8)&7 == m&7
            split_pack(v2, v3, hi, lo);
            *(uint32_t*)(AH + off1) = hi;
            *(uint32_t*)(AL + off1) = lo;
        }
    }
    // ---- W2 chunk 0 ----
    load_w_chunk(WH, WL, W2h, W2l, NOUT2, 128, 0, tid);
    __syncthreads();

    // ---- pass 2: 64 x NOUT2, K = 128, W streamed in 2 chunks ----
    float acc2[2][NT2][4];
    #pragma unroll
    for (int tm = 0; tm < 2; tm++)
        #pragma unroll
        for (int tn = 0; tn < NT2; tn++)
            #pragma unroll
            for (int q = 0; q < 4; q++) acc2[tm][tn][q] = 0.f;

    {
        uint32_t wRB_H[NT2 / 2], wRB_L[NT2 / 2];
        #pragma unroll
        for (int pp = 0; pp < NT2 / 2; pp++) {
            int N0 = warpN * (NOUT2 / 4) + pp * 16;
            wRB_H[pp] = uWH + (N0 + b_row) * 128;
            wRB_L[pp] = uWL + (N0 + b_row) * 128;
        }
        #pragma unroll
        for (int kk = 0; kk < 2; kk++) {
            if (kk > 0) {
                __syncthreads();
                load_w_chunk(WH, WL, W2h, W2l, NOUT2, 128, 1, tid);
                __syncthreads();
            }
            #pragma unroll
            for (int ks = 0; ks < 4; ks++) {
                int gs = kk * 4 + ks;
                uint32_t ao = (uint32_t)(((gs * 2 + g0A) ^ xA) << 4);
                uint32_t wo = (uint32_t)(((ks * 2 + g0W) ^ xW) << 4);
                uint32_t ah[2][4], al[2][4];
                #pragma unroll
                for (int tm = 0; tm < 2; tm++) {
                    LDSM4(ah[tm][0], ah[tm][1], ah[tm][2], ah[tm][3], aRB_H[tm] + ao);
                    LDSM4(al[tm][0], al[tm][1], al[tm][2], al[tm][3], aRB_L[tm] + ao);
                }
                #pragma unroll
                for (int pp = 0; pp < NT2 / 2; pp++) {
                    uint32_t bh[4], bl[4];
                    LDSM4(bh[0], bh[1], bh[2], bh[3], wRB_H[pp] + wo);
                    LDSM4(bl[0], bl[1], bl[2], bl[3], wRB_L[pp] + wo);
                    #pragma unroll
                    for (int hf = 0; hf < 2; hf++) {
                        int tn = pp * 2 + hf;
                        #pragma unroll
                        for (int tm = 0; tm < 2; tm++) {
                            mma16816(acc2[tm][tn], ah[tm], bh + 2 * hf);
                            mma16816(acc2[tm][tn], ah[tm], bl + 2 * hf);
                            mma16816(acc2[tm][tn], al[tm], bh + 2 * hf);
                        }
                    }
                }
            }
        }
    }

    // ---- epilogue: Z + b2 -> global fp32 ----
    float* outF = (K1 == 32) ? (by ? g_z1t : g_z1s) : (by ? g_z2t : g_z2s);
    #pragma unroll
    for (int tm = 0; tm < 2; tm++) {
        int m = warpM * 32 + tm * 16 + lg;
        #pragma unroll
        for (int tn = 0; tn < NT2; tn++) {
            int n = warpN * (NOUT2 / 4) + tn * 8 + lt * 2;
            float2 bv = *(const float2*)(B2 + n);
            int g0 = row0 + m;
            if (g0 < N_NODES) {
                float2 o; o.x = acc2[tm][tn][0] + bv.x; o.y = acc2[tm][tn][1] + bv.y;
                *(float2*)(outF + (size_t)g0 * NOUT2 + n) = o;
            }
            int g1 = row0 + m + 8;
            if (g1 < N_NODES) {
                float2 o; o.x = acc2[tm][tn][2] + bv.x; o.y = acc2[tm][tn][3] + bv.y;
                *(float2*)(outF + (size_t)g1 * NOUT2 + n) = o;
            }
        }
    }
}

// ======================= per-graph 9x9 gram =======================
__global__ void final_kernel(float* __restrict__ out) {
    __shared__ float zs[9 * 64];
    __shared__ float zt[9 * 64];
    int g = blockIdx.x;
    const float4* ps = (const float4*)(g_z2s + (size_t)g * 9 * 64);
    const float4* pt = (const float4*)(g_z2t + (size_t)g * 9 * 64);
    int tid = threadIdx.x;
    for (int i = tid; i < 144; i += 128) {
        ((float4*)zs)[i] = ps[i];
        ((float4*)zt)[i] = pt[i];
    }
    __syncthreads();
    if (tid < 81) {
        int i = tid / 9, j = tid % 9;
        float acc = 0.f;
        #pragma unroll
        for (int k = 0; k < 64; k++) acc += zs[i * 64 + k] * zt[j * 64 + k];
        out[(g * 9 + i) * 9 + j] = acc;
    }
}

// ======================= launch =======================
extern "C" void kernel_launch(void* const* d_in, const int* in_sizes, int n_in,
                              void* d_out, int out_size) {
    const float* x  = (const float*)d_in[0];
    const int*   ei = (const int*)d_in[1];
    const float* B[2][4] = {
        { (const float*)d_in[3],  (const float*)d_in[5],  (const float*)d_in[7],  (const float*)d_in[9]  },
        { (const float*)d_in[11], (const float*)d_in[13], (const float*)d_in[15], (const float*)d_in[17] }
    };
    float* out = (float*)d_out;

    const int SMEM = (2 * 64 * 128 + 2 * 128 * 64) * 2;   // 65536 bytes -> 3 CTA/SM
    cudaFuncSetAttribute(mlp_kernel<32, 4>,  cudaFuncAttributeMaxDynamicSharedMemorySize, SMEM);
    cudaFuncSetAttribute(mlp_kernel<128, 2>, cudaFuncAttributeMaxDynamicSharedMemorySize, SMEM);

    const int GEMM_BLOCKS = (N_NODES + 63) / 64;         // 1407
    const int WARP_BLOCKS = (N_NODES * 32 + 255) / 256;
    const int SCAN_BLOCKS = (N_NODES + 1023) / 1024;     // 88

    // CSR build
    zero_kernel<<<(N_NODES + 255) / 256, 256>>>();
    hist_kernel<<<(N_EDGES + 255) / 256, 256>>>(ei);
    scan1_kernel<<<SCAN_BLOCKS, 1024>>>();
    scan2_kernel<<<1, 128>>>(SCAN_BLOCKS);
    scan3_kernel<<<SCAN_BLOCKS, 1024>>>();
    fill_kernel<<<(N_EDGES + 255) / 256, 256>>>(ei);

    // weight prep (single launch, pointers via kernel args -> capture-safe)
    prep_all_kernel<<<dim3(128, 8), 128>>>(
        (const float*)d_in[2],  (const float*)d_in[4],  (const float*)d_in[6],  (const float*)d_in[8],
        (const float*)d_in[10], (const float*)d_in[12], (const float*)d_in[14], (const float*)d_in[16]);

    agg0_kernel<<<WARP_BLOCKS, 256>>>(x);

    // GIN layer 1 (fused MLP), both branches in one launch
    mlp_kernel<32, 4><<<dim3(GEMM_BLOCKS, 2), 256, SMEM>>>(B[0][0], B[1][0], B[0][1], B[1][1]);

    // layer 2 aggregation (both branches in one pass)
    agg1_kernel<<<WARP_BLOCKS, 256>>>();

    // GIN layer 2 (fused MLP), both branches in one launch
    mlp_kernel<128, 2><<<dim3(GEMM_BLOCKS, 2), 256, SMEM>>>(B[0][2], B[1][2], B[0][3], B[1][3]);

    final_kernel<<<N_GRAPH, 128>>>(out);
}

// round 12
// speedup vs baseline: 1.3575x; 1.0060x over previous
#include <cuda_runtime.h>
#include <cuda_bf16.h>
#include <cstdint>

#define N_NODES 90000
#define N_EDGES 540000
#define IN_F    30
#define N_GRAPH 10000

// ======================= global scratch =======================
__device__ __nv_bfloat16 g_agg0_h[N_NODES * 32];
__device__ __nv_bfloat16 g_agg0_l[N_NODES * 32];
__device__ __nv_bfloat16 g_agg1s_h[N_NODES * 128];
__device__ __nv_bfloat16 g_agg1s_l[N_NODES * 128];
__device__ __nv_bfloat16 g_agg1t_h[N_NODES * 128];
__device__ __nv_bfloat16 g_agg1t_l[N_NODES * 128];
__device__ float g_z1s[N_NODES * 128];
__device__ float g_z1t[N_NODES * 128];
__device__ float g_z2s[N_NODES * 64];
__device__ float g_z2t[N_NODES * 64];
__device__ __nv_bfloat16 g_pwh[2][4][128 * 128];   // prepared weights [branch][layer][n][k]
__device__ __nv_bfloat16 g_pwl[2][4][128 * 128];
__device__ int g_deg[N_NODES];
__device__ int g_cursor[N_NODES];
__device__ int g_rowptr[N_NODES + 1];   // block-local exclusive prefix (+ boff = global)
__device__ int g_csrsrc[N_EDGES];
__device__ int g_bsum[128];
__device__ int g_boff[128];
__device__ int g_scan_ctr;

__device__ __forceinline__ int rowptr_at(int i) {
    return g_rowptr[i] + g_boff[i >> 10];
}

__device__ __forceinline__ void bf16_split(float v, __nv_bfloat16& h, __nv_bfloat16& l) {
    h = __float2bfloat16(v);
    l = __float2bfloat16(v - __bfloat162float(h));
}
__device__ __forceinline__ void split_pack(float v0, float v1, uint32_t& hi, uint32_t& lo) {
    __nv_bfloat16 h0, l0, h1, l1;
    bf16_split(v0, h0, l0);
    bf16_split(v1, h1, l1);
    __nv_bfloat162 ph; ph.x = h0; ph.y = h1;
    __nv_bfloat162 pl; pl.x = l0; pl.y = l1;
    hi = *(uint32_t*)&ph; lo = *(uint32_t*)&pl;
}

// bf16 tensor-core MMA, fp32 accumulate (family-portable, sm_80+)
__device__ __forceinline__ void mma16816(float* d, const uint32_t* a, const uint32_t* b) {
    asm volatile(
        "mma.sync.aligned.m16n8k16.row.col.f32.bf16.bf16.f32 "
        "{%0,%1,%2,%3}, {%4,%5,%6,%7}, {%8,%9}, {%0,%1,%2,%3};\n"
        : "+f"(d[0]), "+f"(d[1]), "+f"(d[2]), "+f"(d[3])
        : "r"(a[0]), "r"(a[1]), "r"(a[2]), "r"(a[3]), "r"(b[0]), "r"(b[1]));
}
#define LDSM4(r0, r1, r2, r3, addr) \
    asm volatile("ldmatrix.sync.aligned.m8n8.x4.shared.b16 {%0,%1,%2,%3}, [%4];" \
        : "=r"(r0), "=r"(r1), "=r"(r2), "=r"(r3) : "r"(addr))

__device__ __forceinline__ uint32_t smem_u32(const void* p) {
    uint32_t a;
    asm("{ .reg .u64 t; cvta.to.shared.u64 t, %1; cvt.u32.u64 %0, t; }" : "=r"(a) : "l"(p));
    return a;
}

// ======================= CSR build =======================
__global__ void hist_kernel(const int* __restrict__ ei) {
    if (blockIdx.x == 0 && threadIdx.x == 0) g_scan_ctr = 0;
    int e = blockIdx.x * blockDim.x + threadIdx.x;
    if (e < N_EDGES) atomicAdd(&g_deg[ei[N_EDGES + e]], 1);
}

// single-pass scan: per-block local scan + last-block scans the 88 block sums
__global__ void scan_kernel() {
    __shared__ int sm[1024];
    __shared__ int isLast;
    int t = threadIdx.x;
    int idx = blockIdx.x * 1024 + t;
    int d = (idx < N_NODES) ? g_deg[idx] : 0;
    sm[t] = d;
    __syncthreads();
    #pragma unroll
    for (int off = 1; off < 1024; off <<= 1) {
        int v = (t >= off) ? sm[t - off] : 0;
        __syncthreads();
        sm[t] += v;
        __syncthreads();
    }
    if (idx < N_NODES) g_rowptr[idx] = sm[t] - d;   // block-local exclusive
    if (t == 1023) g_bsum[blockIdx.x] = sm[1023];
    __threadfence();
    if (t == 0) {
        int done = atomicAdd(&g_scan_ctr, 1);
        isLast = (done == (int)gridDim.x - 1);
    }
    __syncthreads();
    if (!isLast) return;
    // last block: scan the block sums into g_boff (exclusive)
    int nb = gridDim.x;
    int v = (t < nb) ? ((volatile int*)g_bsum)[t] : 0;
    sm[t] = (t < 128) ? v : 0;
    __syncthreads();
    #pragma unroll
    for (int off = 1; off < 128; off <<= 1) {
        int u = (t >= off && t < 128) ? sm[t - off] : 0;
        __syncthreads();
        if (t < 128) sm[t] += u;
        __syncthreads();
    }
    if (t < nb) g_boff[t] = sm[t] - v;
    // rowptr_at(N_NODES) must be N_EDGES: boff index of N_NODES is N_NODES>>10
    if (t == (N_NODES >> 10)) g_rowptr[N_NODES] = N_EDGES - (sm[t] - v);
}

__global__ void fill_kernel(const int* __restrict__ ei) {
    int e = blockIdx.x * blockDim.x + threadIdx.x;
    if (e < N_EDGES) {
        int src = ei[e];
        int dst = ei[N_EDGES + e];
        int pos = rowptr_at(dst) + atomicAdd(&g_cursor[dst], 1);
        g_csrsrc[pos] = src;
    }
}

// ======================= weight prep, all 8 weights in ONE launch =======================
__global__ void prep_all_kernel(
    const float* w0, const float* w1, const float* w2, const float* w3,
    const float* w4, const float* w5, const float* w6, const float* w7)
{
    const int KREAL[4] = { IN_F, 128, 128, 128 };
    const int KSM[4]   = { 32, 128, 128, 128 };
    const int NOUT[4]  = { 128, 128, 128, 64 };
    const float* Ws[8] = { w0, w1, w2, w3, w4, w5, w6, w7 };
    int y = blockIdx.y;
    int br = y >> 2, li = y & 3;
    int n = blockIdx.x;
    int k = threadIdx.x;
    if (n >= NOUT[li] || k >= KSM[li]) return;
    const float* W = Ws[y];
    float v = (k < KREAL[li]) ? W[k * NOUT[li] + n] : 0.f;
    __nv_bfloat16 h, l;
    bf16_split(v, h, l);
    g_pwh[br][li][n * KSM[li] + k] = h;
    g_pwl[br][li][n * KSM[li] + k] = l;
}

// ======================= layer-1 aggregation (index-batched) -> bf16 hi/lo, K pad 32
__global__ void agg0_kernel(const float* __restrict__ x) {
    int w = (blockIdx.x * blockDim.x + threadIdx.x) >> 5;
    int lane = threadIdx.x & 31;
    if (w >= N_NODES) return;
    float acc = (lane < IN_F) ? x[w * IN_F + lane] : 0.f;
    int s0 = rowptr_at(w), s1 = rowptr_at(w + 1);
    for (int e = s0; e < s1; ) {
        int cnt = s1 - e; if (cnt > 8) cnt = 8;
        int idx[8];
        #pragma unroll
        for (int j = 0; j < 8; j++) idx[j] = (j < cnt) ? g_csrsrc[e + j] : 0;
        float v[8];
        #pragma unroll
        for (int j = 0; j < 8; j++)
            v[j] = (j < cnt && lane < IN_F) ? x[idx[j] * IN_F + lane] : 0.f;
        #pragma unroll
        for (int j = 0; j < 8; j++) acc += v[j];
        e += cnt;
    }
    __nv_bfloat16 h, l;
    bf16_split(acc, h, l);
    g_agg0_h[w * 32 + lane] = h;
    g_agg0_l[w * 32 + lane] = l;
}

// ======================= layer-2 aggregation: warp per (node, branch), index-batched
__global__ void agg1_kernel() {
    int br = blockIdx.y;
    const float4* Z = (const float4*)(br ? g_z1t : g_z1s);
    int w = (blockIdx.x * blockDim.x + threadIdx.x) >> 5;
    int lane = threadIdx.x & 31;
    if (w >= N_NODES) return;
    float4 acc = Z[(size_t)w * 32 + lane];
    int s0 = rowptr_at(w), s1 = rowptr_at(w + 1);
    for (int e = s0; e < s1; ) {
        int cnt = s1 - e; if (cnt > 8) cnt = 8;
        int idx[8];
        #pragma unroll
        for (int j = 0; j < 8; j++) idx[j] = (j < cnt) ? g_csrsrc[e + j] : 0;
        float4 v[8];
        #pragma unroll
        for (int j = 0; j < 8; j++)
            v[j] = (j < cnt) ? Z[(size_t)idx[j] * 32 + lane]
                             : make_float4(0.f, 0.f, 0.f, 0.f);
        #pragma unroll
        for (int j = 0; j < 8; j++) {
            acc.x += v[j].x; acc.y += v[j].y; acc.z += v[j].z; acc.w += v[j].w;
        }
        e += cnt;
    }
    uint32_t h01, l01, h23, l23;
    split_pack(acc.x, acc.y, h01, l01);
    split_pack(acc.z, acc.w, h23, l23);
    __nv_bfloat16* dh = br ? g_agg1t_h : g_agg1s_h;
    __nv_bfloat16* dl = br ? g_agg1t_l : g_agg1s_l;
    uint32_t* oh = (uint32_t*)(dh + (size_t)w * 128 + lane * 4);
    uint32_t* ol = (uint32_t*)(dl + (size_t)w * 128 + lane * 4);
    oh[0] = h01; oh[1] = h23;
    ol[0] = l01; ol[1] = l23;
}

// ======================= W chunk loader: 64-col chunk, XOR-swizzled, pitch 64 halfs
__device__ __forceinline__ void load_w_chunk(
    __nv_bfloat16* WH, __nv_bfloat16* WL,
    const __nv_bfloat16* __restrict__ Wh, const __nv_bfloat16* __restrict__ Wl,
    int rows, int KS, int kk, int tid)
{
    for (int i = tid; i < rows * 8; i += 256) {
        int r = i >> 3, g = i & 7;
        int col = kk * 64 + g * 8;
        float4 vh = make_float4(0.f, 0.f, 0.f, 0.f), vl = vh;
        if (col < KS) {
            vh = *(const float4*)(Wh + r * KS + col);
            vl = *(const float4*)(Wl + r * KS + col);
        }
        int dst = r * 64 + ((g ^ (r & 7)) << 3);
        *(float4*)(WH + dst) = vh;
        *(float4*)(WL + dst) = vl;
    }
}

// ======================= fused 2-layer MLP, M-tile 64, 3 CTA/SM (unchanged from R10 win)
template<int K1, int NT2>
__global__ __launch_bounds__(256, 3) void mlp_kernel(
    const float* __restrict__ B1a, const float* __restrict__ B1b,
    const float* __restrict__ B2a, const float* __restrict__ B2b)
{
    constexpr int NOUT2 = NT2 * 32;
    constexpr int GA = K1 / 8;
    constexpr int KCH1 = (K1 + 63) / 64;
    constexpr int KS1 = K1 / 16;
    extern __shared__ char smraw[];
    __nv_bfloat16* AH = (__nv_bfloat16*)smraw;
    __nv_bfloat16* AL = AH + 64 * 128;
    __nv_bfloat16* WH = AL + 64 * 128;
    __nv_bfloat16* WL = WH + 128 * 64;

    int tid = threadIdx.x, lane = tid & 31, wid = tid >> 5;
    int warpM = wid & 1, warpN = wid >> 1;
    int by = blockIdx.y;
    int row0 = blockIdx.x * 64;
    int lg = lane >> 2, lt = lane & 3;

    int l1 = (K1 == 32) ? 0 : 2;
    const __nv_bfloat16* Agh = (K1 == 32) ? g_agg0_h : (by ? g_agg1t_h : g_agg1s_h);
    const __nv_bfloat16* Agl = (K1 == 32) ? g_agg0_l : (by ? g_agg1t_l : g_agg1s_l);
    const __nv_bfloat16* W1h = g_pwh[by][l1];
    const __nv_bfloat16* W1l = g_pwl[by][l1];
    const __nv_bfloat16* W2h = g_pwh[by][l1 + 1];
    const __nv_bfloat16* W2l = g_pwl[by][l1 + 1];
    const float* B1 = by ? B1b : B1a;
    const float* B2 = by ? B2b : B2a;

    // ---- A tile load: XOR swizzle, pitch 128 halfs ----
    for (int i = tid; i < 64 * GA; i += 256) {
        int r = i / GA, g = i % GA;
        int col = g * 8;
        int gr = row0 + r;
        float4 vh = make_float4(0.f, 0.f, 0.f, 0.f), vl = vh;
        if (gr < N_NODES) {
            vh = *(const float4*)(Agh + (size_t)gr * K1 + col);
            vl = *(const float4*)(Agl + (size_t)gr * K1 + col);
        }
        int dst = r * 128 + ((g ^ (r & 7)) << 3);
        *(float4*)(AH + dst) = vh;
        *(float4*)(AL + dst) = vl;
    }
    load_w_chunk(WH, WL, W1h, W1l, 128, K1, 0, tid);
    __syncthreads();

    int a_row = lane & 15;
    int xA = lane & 7;
    int g0A = lane >> 4;
    int b_row = (lane & 7) + ((lane >> 4) & 1) * 8;
    int xW = b_row & 7;
    int g0W = (lane >> 3) & 1;

    uint32_t uAH = smem_u32(AH), uAL = smem_u32(AL);
    uint32_t uWH = smem_u32(WH), uWL = smem_u32(WL);

    uint32_t aRB_H[2], aRB_L[2];
    #pragma unroll
    for (int tm = 0; tm < 2; tm++) {
        int R = warpM * 32 + tm * 16;
        aRB_H[tm] = uAH + (R + a_row) * 256;
        aRB_L[tm] = uAL + (R + a_row) * 256;
    }

    // ---- pass 1 ----
    float acc[2][4][4];
    #pragma unroll
    for (int tm = 0; tm < 2; tm++)
        #pragma unroll
        for (int tn = 0; tn < 4; tn++)
            #pragma unroll
            for (int q = 0; q < 4; q++) acc[tm][tn][q] = 0.f;

    {
        uint32_t wRB_H[2], wRB_L[2];
        #pragma unroll
        for (int pp = 0; pp < 2; pp++) {
            int N0 = warpN * 32 + pp * 16;
            wRB_H[pp] = uWH + (N0 + b_row) * 128;
            wRB_L[pp] = uWL + (N0 + b_row) * 128;
        }
        constexpr int NKS = (KCH1 == 1) ? KS1 : 4;
        #pragma unroll
        for (int kk = 0; kk < KCH1; kk++) {
            if (kk > 0) {
                __syncthreads();
                load_w_chunk(WH, WL, W1h, W1l, 128, K1, kk, tid);
                __syncthreads();
            }
            #pragma unroll
            for (int ks = 0; ks < NKS; ks++) {
                int gs = kk * 4 + ks;
                uint32_t ao = (uint32_t)(((gs * 2 + g0A) ^ xA) << 4);
                uint32_t wo = (uint32_t)(((ks * 2 + g0W) ^ xW) << 4);
                uint32_t ah[2][4], al[2][4];
                #pragma unroll
                for (int tm = 0; tm < 2; tm++) {
                    LDSM4(ah[tm][0], ah[tm][1], ah[tm][2], ah[tm][3], aRB_H[tm] + ao);
                    LDSM4(al[tm][0], al[tm][1], al[tm][2], al[tm][3], aRB_L[tm] + ao);
                }
                #pragma unroll
                for (int pp = 0; pp < 2; pp++) {
                    uint32_t bh[4], bl[4];
                    LDSM4(bh[0], bh[1], bh[2], bh[3], wRB_H[pp] + wo);
                    LDSM4(bl[0], bl[1], bl[2], bl[3], wRB_L[pp] + wo);
                    #pragma unroll
                    for (int hf = 0; hf < 2; hf++) {
                        int tn = pp * 2 + hf;
                        #pragma unroll
                        for (int tm = 0; tm < 2; tm++) {
                            mma16816(acc[tm][tn], ah[tm], bh + 2 * hf);
                            mma16816(acc[tm][tn], ah[tm], bl + 2 * hf);
                            mma16816(acc[tm][tn], al[tm], bh + 2 * hf);
                        }
                    }
                }
            }
        }
    }
    __syncthreads();

    // ---- stage H = relu(acc + b1) -> A region (swizzled) ----
    #pragma unroll
    for (int tm = 0; tm < 2; tm++) {
        int m = warpM * 32 + tm * 16 + lg;
        #pragma unroll
        for (int tn = 0; tn < 4; tn++) {
            int n = warpN * 32 + tn * 8 + lt * 2;
            float2 bv = *(const float2*)(B1 + n);
            float v0 = fmaxf(acc[tm][tn][0] + bv.x, 0.f);
            float v1 = fmaxf(acc[tm][tn][1] + bv.y, 0.f);
            float v2 = fmaxf(acc[tm][tn][2] + bv.x, 0.f);
            float v3 = fmaxf(acc[tm][tn][3] + bv.y, 0.f);
            uint32_t hi, lo;
            int off0 = m * 128 + (((n >> 3) ^ (m & 7)) << 3) + (n & 7);
            split_pack(v0, v1, hi, lo);
            *(uint32_t*)(AH + off0) = hi;
            *(uint32_t*)(AL + off0) = lo;
            int off1 = (m + 8) * 128 + (((n >> 3) ^ (m & 7)) << 3) + (n & 7);
            split_pack(v2, v3, hi, lo);
            *(uint32_t*)(AH + off1) = hi;
            *(uint32_t*)(AL + off1) = lo;
        }
    }
    load_w_chunk(WH, WL, W2h, W2l, NOUT2, 128, 0, tid);
    __syncthreads();

    // ---- pass 2 ----
    float acc2[2][NT2][4];
    #pragma unroll
    for (int tm = 0; tm < 2; tm++)
        #pragma unroll
        for (int tn = 0; tn < NT2; tn++)
            #pragma unroll
            for (int q = 0; q < 4; q++) acc2[tm][tn][q] = 0.f;

    {
        uint32_t wRB_H[NT2 / 2], wRB_L[NT2 / 2];
        #pragma unroll
        for (int pp = 0; pp < NT2 / 2; pp++) {
            int N0 = warpN * (NOUT2 / 4) + pp * 16;
            wRB_H[pp] = uWH + (N0 + b_row) * 128;
            wRB_L[pp] = uWL + (N0 + b_row) * 128;
        }
        #pragma unroll
        for (int kk = 0; kk < 2; kk++) {
            if (kk > 0) {
                __syncthreads();
                load_w_chunk(WH, WL, W2h, W2l, NOUT2, 128, 1, tid);
                __syncthreads();
            }
            #pragma unroll
            for (int ks = 0; ks < 4; ks++) {
                int gs = kk * 4 + ks;
                uint32_t ao = (uint32_t)(((gs * 2 + g0A) ^ xA) << 4);
                uint32_t wo = (uint32_t)(((ks * 2 + g0W) ^ xW) << 4);
                uint32_t ah[2][4], al[2][4];
                #pragma unroll
                for (int tm = 0; tm < 2; tm++) {
                    LDSM4(ah[tm][0], ah[tm][1], ah[tm][2], ah[tm][3], aRB_H[tm] + ao);
                    LDSM4(al[tm][0], al[tm][1], al[tm][2], al[tm][3], aRB_L[tm] + ao);
                }
                #pragma unroll
                for (int pp = 0; pp < NT2 / 2; pp++) {
                    uint32_t bh[4], bl[4];
                    LDSM4(bh[0], bh[1], bh[2], bh[3], wRB_H[pp] + wo);
                    LDSM4(bl[0], bl[1], bl[2], bl[3], wRB_L[pp] + wo);
                    #pragma unroll
                    for (int hf = 0; hf < 2; hf++) {
                        int tn = pp * 2 + hf;
                        #pragma unroll
                        for (int tm = 0; tm < 2; tm++) {
                            mma16816(acc2[tm][tn], ah[tm], bh + 2 * hf);
                            mma16816(acc2[tm][tn], ah[tm], bl + 2 * hf);
                            mma16816(acc2[tm][tn], al[tm], bh + 2 * hf);
                        }
                    }
                }
            }
        }
    }

    // ---- epilogue ----
    float* outF = (K1 == 32) ? (by ? g_z1t : g_z1s) : (by ? g_z2t : g_z2s);
    #pragma unroll
    for (int tm = 0; tm < 2; tm++) {
        int m = warpM * 32 + tm * 16 + lg;
        #pragma unroll
        for (int tn = 0; tn < NT2; tn++) {
            int n = warpN * (NOUT2 / 4) + tn * 8 + lt * 2;
            float2 bv = *(const float2*)(B2 + n);
            int g0 = row0 + m;
            if (g0 < N_NODES) {
                float2 o; o.x = acc2[tm][tn][0] + bv.x; o.y = acc2[tm][tn][1] + bv.y;
                *(float2*)(outF + (size_t)g0 * NOUT2 + n) = o;
            }
            int g1 = row0 + m + 8;
            if (g1 < N_NODES) {
                float2 o; o.x = acc2[tm][tn][2] + bv.x; o.y = acc2[tm][tn][3] + bv.y;
                *(float2*)(outF + (size_t)g1 * NOUT2 + n) = o;
            }
        }
    }
}

// ======================= per-graph 9x9 gram: 2 graphs per block =======================
__global__ void final_kernel(float* __restrict__ out) {
    __shared__ float zs[2][9 * 64];
    __shared__ float zt[2][9 * 64];
    int g0 = blockIdx.x * 2;
    int tid = threadIdx.x;
    const float4* ps = (const float4*)(g_z2s + (size_t)g0 * 9 * 64);
    const float4* pt = (const float4*)(g_z2t + (size_t)g0 * 9 * 64);
    for (int i = tid; i < 288; i += 256) {
        int gg = i / 144, r = i % 144;
        ((float4*)zs[gg])[r] = ps[i];
        ((float4*)zt)[i] = pt[i];   // zs/zt contiguous 2x144 float4 each
    }
    __syncthreads();
    int gg = tid >> 7, t = tid & 127;
    if (t < 81) {
        int i = t / 9, j = t % 9;
        float acc = 0.f;
        #pragma unroll
        for (int k = 0; k < 64; k++) acc += zs[gg][i * 64 + k] * zt[gg][j * 64 + k];
        out[((g0 + gg) * 9 + i) * 9 + j] = acc;
    }
}

// ======================= launch =======================
extern "C" void kernel_launch(void* const* d_in, const int* in_sizes, int n_in,
                              void* d_out, int out_size) {
    const float* x  = (const float*)d_in[0];
    const int*   ei = (const int*)d_in[1];
    const float* B[2][4] = {
        { (const float*)d_in[3],  (const float*)d_in[5],  (const float*)d_in[7],  (const float*)d_in[9]  },
        { (const float*)d_in[11], (const float*)d_in[13], (const float*)d_in[15], (const float*)d_in[17] }
    };
    float* out = (float*)d_out;

    const int SMEM = (2 * 64 * 128 + 2 * 128 * 64) * 2;   // 65536 bytes -> 3 CTA/SM
    cudaFuncSetAttribute(mlp_kernel<32, 4>,  cudaFuncAttributeMaxDynamicSharedMemorySize, SMEM);
    cudaFuncSetAttribute(mlp_kernel<128, 2>, cudaFuncAttributeMaxDynamicSharedMemorySize, SMEM);

    const int GEMM_BLOCKS = (N_NODES + 63) / 64;         // 1407
    const int WARP_BLOCKS = (N_NODES * 32 + 255) / 256;
    const int SCAN_BLOCKS = (N_NODES + 1023) / 1024;     // 88

    // zero deg/cursor via memset nodes (capture-legal, full BW)
    void *p_deg = nullptr, *p_cur = nullptr;
    cudaGetSymbolAddress(&p_deg, g_deg);
    cudaGetSymbolAddress(&p_cur, g_cursor);
    cudaMemsetAsync(p_deg, 0, N_NODES * sizeof(int));
    cudaMemsetAsync(p_cur, 0, N_NODES * sizeof(int));

    // CSR build (single-pass scan)
    hist_kernel<<<(N_EDGES + 255) / 256, 256>>>(ei);
    scan_kernel<<<SCAN_BLOCKS, 1024>>>();
    fill_kernel<<<(N_EDGES + 255) / 256, 256>>>(ei);

    // weight prep (single launch, pointers via kernel args -> capture-safe)
    prep_all_kernel<<<dim3(128, 8), 128>>>(
        (const float*)d_in[2],  (const float*)d_in[4],  (const float*)d_in[6],  (const float*)d_in[8],
        (const float*)d_in[10], (const float*)d_in[12], (const float*)d_in[14], (const float*)d_in[16]);

    agg0_kernel<<<WARP_BLOCKS, 256>>>(x);

    // GIN layer 1 (fused MLP), both branches in one launch
    mlp_kernel<32, 4><<<dim3(GEMM_BLOCKS, 2), 256, SMEM>>>(B[0][0], B[1][0], B[0][1], B[1][1]);

    // layer 2 aggregation: warp per (node, branch)
    agg1_kernel<<<dim3(WARP_BLOCKS, 2), 256>>>();

    // GIN layer 2 (fused MLP), both branches in one launch
    mlp_kernel<128, 2><<<dim3(GEMM_BLOCKS, 2), 256, SMEM>>>(B[0][2], B[1][2], B[0][3], B[1][3]);

    final_kernel<<<(N_GRAPH + 1) / 2, 256>>>(out);
}

// round 13
// speedup vs baseline: 1.5145x; 1.1156x over previous
#include <cuda_runtime.h>
#include <cuda_fp16.h>
#include <cstdint>

#define N_NODES 90000
#define N_EDGES 540000
#define IN_F    30
#define N_GRAPH 10000

// ======================= global scratch =======================
__device__ __half g_agg0[N_NODES * 32];
__device__ __half g_agg1s[N_NODES * 128];
__device__ __half g_agg1t[N_NODES * 128];
__device__ float g_z1s[N_NODES * 128];
__device__ float g_z1t[N_NODES * 128];
__device__ float g_z2s[N_NODES * 64];
__device__ float g_z2t[N_NODES * 64];
__device__ __half g_pwh[2][4][128 * 128];   // prepared weights [branch][layer][n][k], hi
__device__ __half g_pwl[2][4][128 * 128];   // lo residual
__device__ int g_deg[N_NODES];
__device__ int g_cursor[N_NODES];
__device__ int g_rowptr[N_NODES + 1];   // block-local exclusive prefix (+ boff = global)
__device__ int g_csrsrc[N_EDGES];
__device__ int g_bsum[128];
__device__ int g_boff[128];
__device__ int g_scan_ctr;

__device__ __forceinline__ int rowptr_at(int i) {
    return g_rowptr[i] + g_boff[i >> 10];
}

__device__ __forceinline__ void fp16_split(float v, __half& h, __half& l) {
    h = __float2half(v);
    l = __float2half(v - __half2float(h));
}

// fp16 tensor-core MMA, fp32 accumulate (family-portable, sm_80+)
__device__ __forceinline__ void mma16816(float* d, const uint32_t* a, const uint32_t* b) {
    asm volatile(
        "mma.sync.aligned.m16n8k16.row.col.f32.f16.f16.f32 "
        "{%0,%1,%2,%3}, {%4,%5,%6,%7}, {%8,%9}, {%0,%1,%2,%3};\n"
        : "+f"(d[0]), "+f"(d[1]), "+f"(d[2]), "+f"(d[3])
        : "r"(a[0]), "r"(a[1]), "r"(a[2]), "r"(a[3]), "r"(b[0]), "r"(b[1]));
}
#define LDSM4(r0, r1, r2, r3, addr) \
    asm volatile("ldmatrix.sync.aligned.m8n8.x4.shared.b16 {%0,%1,%2,%3}, [%4];" \
        : "=r"(r0), "=r"(r1), "=r"(r2), "=r"(r3) : "r"(addr))

__device__ __forceinline__ uint32_t smem_u32(const void* p) {
    uint32_t a;
    asm("{ .reg .u64 t; cvta.to.shared.u64 t, %1; cvt.u32.u64 %0, t; }" : "=r"(a) : "l"(p));
    return a;
}

// ======================= CSR build =======================
__global__ void hist_kernel(const int* __restrict__ ei) {
    if (blockIdx.x == 0 && threadIdx.x == 0) g_scan_ctr = 0;
    int e = blockIdx.x * blockDim.x + threadIdx.x;
    if (e < N_EDGES) atomicAdd(&g_deg[ei[N_EDGES + e]], 1);
}

// single-pass scan: per-block local scan + last-block scans the 88 block sums
__global__ void scan_kernel() {
    __shared__ int sm[1024];
    __shared__ int isLast;
    int t = threadIdx.x;
    int idx = blockIdx.x * 1024 + t;
    int d = (idx < N_NODES) ? g_deg[idx] : 0;
    sm[t] = d;
    __syncthreads();
    #pragma unroll
    for (int off = 1; off < 1024; off <<= 1) {
        int v = (t >= off) ? sm[t - off] : 0;
        __syncthreads();
        sm[t] += v;
        __syncthreads();
    }
    if (idx < N_NODES) g_rowptr[idx] = sm[t] - d;
    if (t == 1023) g_bsum[blockIdx.x] = sm[1023];
    __threadfence();
    if (t == 0) {
        int done = atomicAdd(&g_scan_ctr, 1);
        isLast = (done == (int)gridDim.x - 1);
    }
    __syncthreads();
    if (!isLast) return;
    int nb = gridDim.x;
    int v = (t < nb) ? ((volatile int*)g_bsum)[t] : 0;
    sm[t] = (t < 128) ? v : 0;
    __syncthreads();
    #pragma unroll
    for (int off = 1; off < 128; off <<= 1) {
        int u = (t >= off && t < 128) ? sm[t - off] : 0;
        __syncthreads();
        if (t < 128) sm[t] += u;
        __syncthreads();
    }
    if (t < nb) g_boff[t] = sm[t] - v;
    if (t == (N_NODES >> 10)) g_rowptr[N_NODES] = N_EDGES - (sm[t] - v);
}

__global__ void fill_kernel(const int* __restrict__ ei) {
    int e = blockIdx.x * blockDim.x + threadIdx.x;
    if (e < N_EDGES) {
        int src = ei[e];
        int dst = ei[N_EDGES + e];
        int pos = rowptr_at(dst) + atomicAdd(&g_cursor[dst], 1);
        g_csrsrc[pos] = src;
    }
}

// ======================= weight prep, all 8 weights in ONE launch =======================
__global__ void prep_all_kernel(
    const float* w0, const float* w1, const float* w2, const float* w3,
    const float* w4, const float* w5, const float* w6, const float* w7)
{
    const int KREAL[4] = { IN_F, 128, 128, 128 };
    const int KSM[4]   = { 32, 128, 128, 128 };
    const int NOUT[4]  = { 128, 128, 128, 64 };
    const float* Ws[8] = { w0, w1, w2, w3, w4, w5, w6, w7 };
    int y = blockIdx.y;
    int br = y >> 2, li = y & 3;
    int n = blockIdx.x;
    int k = threadIdx.x;
    if (n >= NOUT[li] || k >= KSM[li]) return;
    const float* W = Ws[y];
    float v = (k < KREAL[li]) ? W[k * NOUT[li] + n] : 0.f;
    __half h, l;
    fp16_split(v, h, l);
    g_pwh[br][li][n * KSM[li] + k] = h;
    g_pwl[br][li][n * KSM[li] + k] = l;
}

// ======================= layer-1 aggregation (index-batched) -> fp16, K pad 32
__global__ void agg0_kernel(const float* __restrict__ x) {
    int w = (blockIdx.x * blockDim.x + threadIdx.x) >> 5;
    int lane = threadIdx.x & 31;
    if (w >= N_NODES) return;
    float acc = (lane < IN_F) ? x[w * IN_F + lane] : 0.f;
    int s0 = rowptr_at(w), s1 = rowptr_at(w + 1);
    for (int e = s0; e < s1; ) {
        int cnt = s1 - e; if (cnt > 8) cnt = 8;
        int idx[8];
        #pragma unroll
        for (int j = 0; j < 8; j++) idx[j] = (j < cnt) ? g_csrsrc[e + j] : 0;
        float v[8];
        #pragma unroll
        for (int j = 0; j < 8; j++)
            v[j] = (j < cnt && lane < IN_F) ? x[idx[j] * IN_F + lane] : 0.f;
        #pragma unroll
        for (int j = 0; j < 8; j++) acc += v[j];
        e += cnt;
    }
    g_agg0[w * 32 + lane] = __float2half(acc);
}

// ======================= layer-2 aggregation: warp per (node, branch), index-batched
__global__ void agg1_kernel() {
    int br = blockIdx.y;
    const float4* Z = (const float4*)(br ? g_z1t : g_z1s);
    int w = (blockIdx.x * blockDim.x + threadIdx.x) >> 5;
    int lane = threadIdx.x & 31;
    if (w >= N_NODES) return;
    float4 acc = Z[(size_t)w * 32 + lane];
    int s0 = rowptr_at(w), s1 = rowptr_at(w + 1);
    for (int e = s0; e < s1; ) {
        int cnt = s1 - e; if (cnt > 8) cnt = 8;
        int idx[8];
        #pragma unroll
        for (int j = 0; j < 8; j++) idx[j] = (j < cnt) ? g_csrsrc[e + j] : 0;
        float4 v[8];
        #pragma unroll
        for (int j = 0; j < 8; j++)
            v[j] = (j < cnt) ? Z[(size_t)idx[j] * 32 + lane]
                             : make_float4(0.f, 0.f, 0.f, 0.f);
        #pragma unroll
        for (int j = 0; j < 8; j++) {
            acc.x += v[j].x; acc.y += v[j].y; acc.z += v[j].z; acc.w += v[j].w;
        }
        e += cnt;
    }
    __half2 p01 = __floats2half2_rn(acc.x, acc.y);
    __half2 p23 = __floats2half2_rn(acc.z, acc.w);
    __half* dst = br ? g_agg1t : g_agg1s;
    uint32_t* o = (uint32_t*)(dst + (size_t)w * 128 + lane * 4);
    o[0] = *(uint32_t*)&p01;
    o[1] = *(uint32_t*)&p23;
}

// ======================= W chunk loader: 64-col chunk, XOR-swizzled, pitch 64 halfs
__device__ __forceinline__ void load_w_chunk(
    __half* WH, __half* WL,
    const __half* __restrict__ Wh, const __half* __restrict__ Wl,
    int rows, int KS, int kk, int tid)
{
    for (int i = tid; i < rows * 8; i += 256) {
        int r = i >> 3, g = i & 7;
        int col = kk * 64 + g * 8;
        float4 vh = make_float4(0.f, 0.f, 0.f, 0.f), vl = vh;
        if (col < KS) {
            vh = *(const float4*)(Wh + r * KS + col);
            vl = *(const float4*)(Wl + r * KS + col);
        }
        int dst = r * 64 + ((g ^ (r & 7)) << 3);
        *(float4*)(WH + dst) = vh;
        *(float4*)(WL + dst) = vl;
    }
}

// ======================= fused 2-layer MLP, M-tile 64, 3 CTA/SM =======================
// fp16 scheme: A single-precision-fp16, W split hi/lo. D = A*Wh + A*Wl (2 MMAs/step).
// smem: A 64x128 halfs (16 KB) + W hi/lo 2x(128x64) halfs (32 KB) = 48 KB.
template<int K1, int NT2>
__global__ __launch_bounds__(256, 3) void mlp_kernel(
    const float* __restrict__ B1a, const float* __restrict__ B1b,
    const float* __restrict__ B2a, const float* __restrict__ B2b)
{
    constexpr int NOUT2 = NT2 * 32;
    constexpr int GA = K1 / 8;
    constexpr int KCH1 = (K1 + 63) / 64;
    constexpr int KS1 = K1 / 16;
    extern __shared__ char smraw[];
    __half* AS = (__half*)smraw;          // 8192 halfs
    __half* WH = AS + 64 * 128;           // 8192 halfs
    __half* WL = WH + 128 * 64;           // 8192 halfs

    int tid = threadIdx.x, lane = tid & 31, wid = tid >> 5;
    int warpM = wid & 1, warpN = wid >> 1;
    int by = blockIdx.y;
    int row0 = blockIdx.x * 64;
    int lg = lane >> 2, lt = lane & 3;

    int l1 = (K1 == 32) ? 0 : 2;
    const __half* Ag = (K1 == 32) ? g_agg0 : (by ? g_agg1t : g_agg1s);
    const __half* W1h = g_pwh[by][l1];
    const __half* W1l = g_pwl[by][l1];
    const __half* W2h = g_pwh[by][l1 + 1];
    const __half* W2l = g_pwl[by][l1 + 1];
    const float* B1 = by ? B1b : B1a;
    const float* B2 = by ? B2b : B2a;

    // ---- A tile load: XOR swizzle, pitch 128 halfs ----
    for (int i = tid; i < 64 * GA; i += 256) {
        int r = i / GA, g = i % GA;
        int col = g * 8;
        int gr = row0 + r;
        float4 v = make_float4(0.f, 0.f, 0.f, 0.f);
        if (gr < N_NODES) v = *(const float4*)(Ag + (size_t)gr * K1 + col);
        int dst = r * 128 + ((g ^ (r & 7)) << 3);
        *(float4*)(AS + dst) = v;
    }
    load_w_chunk(WH, WL, W1h, W1l, 128, K1, 0, tid);
    __syncthreads();

    int a_row = lane & 15;
    int xA = lane & 7;
    int g0A = lane >> 4;
    int b_row = (lane & 7) + ((lane >> 4) & 1) * 8;
    int xW = b_row & 7;
    int g0W = (lane >> 3) & 1;

    uint32_t uAS = smem_u32(AS);
    uint32_t uWH = smem_u32(WH), uWL = smem_u32(WL);

    uint32_t aRB[2];
    #pragma unroll
    for (int tm = 0; tm < 2; tm++) {
        int R = warpM * 32 + tm * 16;
        aRB[tm] = uAS + (R + a_row) * 256;
    }

    // ---- pass 1: 64 x 128, warp tile 32 x 32 ----
    float acc[2][4][4];
    #pragma unroll
    for (int tm = 0; tm < 2; tm++)
        #pragma unroll
        for (int tn = 0; tn < 4; tn++)
            #pragma unroll
            for (int q = 0; q < 4; q++) acc[tm][tn][q] = 0.f;

    {
        uint32_t wRB_H[2], wRB_L[2];
        #pragma unroll
        for (int pp = 0; pp < 2; pp++) {
            int N0 = warpN * 32 + pp * 16;
            wRB_H[pp] = uWH + (N0 + b_row) * 128;
            wRB_L[pp] = uWL + (N0 + b_row) * 128;
        }
        constexpr int NKS = (KCH1 == 1) ? KS1 : 4;
        #pragma unroll
        for (int kk = 0; kk < KCH1; kk++) {
            if (kk > 0) {
                __syncthreads();
                load_w_chunk(WH, WL, W1h, W1l, 128, K1, kk, tid);
                __syncthreads();
            }
            #pragma unroll
            for (int ks = 0; ks < NKS; ks++) {
                int gs = kk * 4 + ks;
                uint32_t ao = (uint32_t)(((gs * 2 + g0A) ^ xA) << 4);
                uint32_t wo = (uint32_t)(((ks * 2 + g0W) ^ xW) << 4);
                uint32_t a[2][4];
                #pragma unroll
                for (int tm = 0; tm < 2; tm++)
                    LDSM4(a[tm][0], a[tm][1], a[tm][2], a[tm][3], aRB[tm] + ao);
                #pragma unroll
                for (int pp = 0; pp < 2; pp++) {
                    uint32_t bh[4], bl[4];
                    LDSM4(bh[0], bh[1], bh[2], bh[3], wRB_H[pp] + wo);
                    LDSM4(bl[0], bl[1], bl[2], bl[3], wRB_L[pp] + wo);
                    #pragma unroll
                    for (int hf = 0; hf < 2; hf++) {
                        int tn = pp * 2 + hf;
                        #pragma unroll
                        for (int tm = 0; tm < 2; tm++) {
                            mma16816(acc[tm][tn], a[tm], bh + 2 * hf);
                            mma16816(acc[tm][tn], a[tm], bl + 2 * hf);
                        }
                    }
                }
            }
        }
    }
    __syncthreads();

    // ---- stage H = relu(acc + b1) -> A region (swizzled, fp16 single) ----
    #pragma unroll
    for (int tm = 0; tm < 2; tm++) {
        int m = warpM * 32 + tm * 16 + lg;
        #pragma unroll
        for (int tn = 0; tn < 4; tn++) {
            int n = warpN * 32 + tn * 8 + lt * 2;
            float2 bv = *(const float2*)(B1 + n);
            float v0 = fmaxf(acc[tm][tn][0] + bv.x, 0.f);
            float v1 = fmaxf(acc[tm][tn][1] + bv.y, 0.f);
            float v2 = fmaxf(acc[tm][tn][2] + bv.x, 0.f);
            float v3 = fmaxf(acc[tm][tn][3] + bv.y, 0.f);
            int off0 = m * 128 + (((n >> 3) ^ (m & 7)) << 3) + (n & 7);
            __half2 p0 = __floats2half2_rn(v0, v1);
            *(uint32_t*)(AS + off0) = *(uint32_t*)&p0;
            int off1 = (m + 8) * 128 + (((n >> 3) ^ (m & 7)) << 3) + (n & 7);
            __half2 p1 = __floats2half2_rn(v2, v3);
            *(uint32_t*)(AS + off1) = *(uint32_t*)&p1;
        }
    }
    load_w_chunk(WH, WL, W2h, W2l, NOUT2, 128, 0, tid);
    __syncthreads();

    // ---- pass 2: 64 x NOUT2, K = 128 ----
    float acc2[2][NT2][4];
    #pragma unroll
    for (int tm = 0; tm < 2; tm++)
        #pragma unroll
        for (int tn = 0; tn < NT2; tn++)
            #pragma unroll
            for (int q = 0; q < 4; q++) acc2[tm][tn][q] = 0.f;

    {
        uint32_t wRB_H[NT2 / 2], wRB_L[NT2 / 2];
        #pragma unroll
        for (int pp = 0; pp < NT2 / 2; pp++) {
            int N0 = warpN * (NOUT2 / 4) + pp * 16;
            wRB_H[pp] = uWH + (N0 + b_row) * 128;
            wRB_L[pp] = uWL + (N0 + b_row) * 128;
        }
        #pragma unroll
        for (int kk = 0; kk < 2; kk++) {
            if (kk > 0) {
                __syncthreads();
                load_w_chunk(WH, WL, W2h, W2l, NOUT2, 128, 1, tid);
                __syncthreads();
            }
            #pragma unroll
            for (int ks = 0; ks < 4; ks++) {
                int gs = kk * 4 + ks;
                uint32_t ao = (uint32_t)(((gs * 2 + g0A) ^ xA) << 4);
                uint32_t wo = (uint32_t)(((ks * 2 + g0W) ^ xW) << 4);
                uint32_t a[2][4];
                #pragma unroll
                for (int tm = 0; tm < 2; tm++)
                    LDSM4(a[tm][0], a[tm][1], a[tm][2], a[tm][3], aRB[tm] + ao);
                #pragma unroll
                for (int pp = 0; pp < NT2 / 2; pp++) {
                    uint32_t bh[4], bl[4];
                    LDSM4(bh[0], bh[1], bh[2], bh[3], wRB_H[pp] + wo);
                    LDSM4(bl[0], bl[1], bl[2], bl[3], wRB_L[pp] + wo);
                    #pragma unroll
                    for (int hf = 0; hf < 2; hf++) {
                        int tn = pp * 2 + hf;
                        #pragma unroll
                        for (int tm = 0; tm < 2; tm++) {
                            mma16816(acc2[tm][tn], a[tm], bh + 2 * hf);
                            mma16816(acc2[tm][tn], a[tm], bl + 2 * hf);
                        }
                    }
                }
            }
        }
    }

    // ---- epilogue: Z + b2 -> global fp32 ----
    float* outF = (K1 == 32) ? (by ? g_z1t : g_z1s) : (by ? g_z2t : g_z2s);
    #pragma unroll
    for (int tm = 0; tm < 2; tm++) {
        int m = warpM * 32 + tm * 16 + lg;
        #pragma unroll
        for (int tn = 0; tn < NT2; tn++) {
            int n = warpN * (NOUT2 / 4) + tn * 8 + lt * 2;
            float2 bv = *(const float2*)(B2 + n);
            int g0 = row0 + m;
            if (g0 < N_NODES) {
                float2 o; o.x = acc2[tm][tn][0] + bv.x; o.y = acc2[tm][tn][1] + bv.y;
                *(float2*)(outF + (size_t)g0 * NOUT2 + n) = o;
            }
            int g1 = row0 + m + 8;
            if (g1 < N_NODES) {
                float2 o; o.x = acc2[tm][tn][2] + bv.x; o.y = acc2[tm][tn][3] + bv.y;
                *(float2*)(outF + (size_t)g1 * NOUT2 + n) = o;
            }
        }
    }
}

// ======================= per-graph 9x9 gram: 2 graphs per block =======================
__global__ void final_kernel(float* __restrict__ out) {
    __shared__ float zs[2][9 * 64];
    __shared__ float zt[2][9 * 64];
    int g0 = blockIdx.x * 2;
    int tid = threadIdx.x;
    const float4* ps = (const float4*)(g_z2s + (size_t)g0 * 9 * 64);
    const float4* pt = (const float4*)(g_z2t + (size_t)g0 * 9 * 64);
    for (int i = tid; i < 288; i += 256) {
        ((float4*)zs)[i] = ps[i];
        ((float4*)zt)[i] = pt[i];
    }
    __syncthreads();
    int gg = tid >> 7, t = tid & 127;
    if (t < 81) {
        int i = t / 9, j = t % 9;
        float acc = 0.f;
        #pragma unroll
        for (int k = 0; k < 64; k++) acc += zs[gg][i * 64 + k] * zt[gg][j * 64 + k];
        out[((g0 + gg) * 9 + i) * 9 + j] = acc;
    }
}

// ======================= launch =======================
extern "C" void kernel_launch(void* const* d_in, const int* in_sizes, int n_in,
                              void* d_out, int out_size) {
    const float* x  = (const float*)d_in[0];
    const int*   ei = (const int*)d_in[1];
    const float* B[2][4] = {
        { (const float*)d_in[3],  (const float*)d_in[5],  (const float*)d_in[7],  (const float*)d_in[9]  },
        { (const float*)d_in[11], (const float*)d_in[13], (const float*)d_in[15], (const float*)d_in[17] }
    };
    float* out = (float*)d_out;

    const int SMEM = (64 * 128 + 2 * 128 * 64) * 2;   // 49152 bytes -> 3+ CTA/SM
    cudaFuncSetAttribute(mlp_kernel<32, 4>,  cudaFuncAttributeMaxDynamicSharedMemorySize, SMEM);
    cudaFuncSetAttribute(mlp_kernel<128, 2>, cudaFuncAttributeMaxDynamicSharedMemorySize, SMEM);

    const int GEMM_BLOCKS = (N_NODES + 63) / 64;         // 1407
    const int WARP_BLOCKS = (N_NODES * 32 + 255) / 256;
    const int SCAN_BLOCKS = (N_NODES + 1023) / 1024;     // 88

    // zero deg/cursor via memset nodes (capture-legal, full BW)
    void *p_deg = nullptr, *p_cur = nullptr;
    cudaGetSymbolAddress(&p_deg, g_deg);
    cudaGetSymbolAddress(&p_cur, g_cursor);
    cudaMemsetAsync(p_deg, 0, N_NODES * sizeof(int));
    cudaMemsetAsync(p_cur, 0, N_NODES * sizeof(int));

    // CSR build (single-pass scan)
    hist_kernel<<<(N_EDGES + 255) / 256, 256>>>(ei);
    scan_kernel<<<SCAN_BLOCKS, 1024>>>();
    fill_kernel<<<(N_EDGES + 255) / 256, 256>>>(ei);

    // weight prep (single launch, pointers via kernel args -> capture-safe)
    prep_all_kernel<<<dim3(128, 8), 128>>>(
        (const float*)d_in[2],  (const float*)d_in[4],  (const float*)d_in[6],  (const float*)d_in[8],
        (const float*)d_in[10], (const float*)d_in[12], (const float*)d_in[14], (const float*)d_in[16]);

    agg0_kernel<<<WARP_BLOCKS, 256>>>(x);

    // GIN layer 1 (fused MLP), both branches in one launch
    mlp_kernel<32, 4><<<dim3(GEMM_BLOCKS, 2), 256, SMEM>>>(B[0][0], B[1][0], B[0][1], B[1][1]);

    // layer 2 aggregation: warp per (node, branch)
    agg1_kernel<<<dim3(WARP_BLOCKS, 2), 256>>>();

    // GIN layer 2 (fused MLP), both branches in one launch
    mlp_kernel<128, 2><<<dim3(GEMM_BLOCKS, 2), 256, SMEM>>>(B[0][2], B[1][2], B[0][3], B[1][3]);

    final_kernel<<<(N_GRAPH + 1) / 2, 256>>>(out);
}

// round 14
// speedup vs baseline: 1.5598x; 1.0299x over previous
#include <cuda_runtime.h>
#include <cuda_fp16.h>
#include <cstdint>

#define N_NODES 90000
#define N_EDGES 540000
#define IN_F    30
#define N_GRAPH 10000

// ======================= global scratch =======================
__device__ __half g_agg0_h[N_NODES * 32];
__device__ __half g_agg0_l[N_NODES * 32];
__device__ __half g_agg1s[N_NODES * 128];
__device__ __half g_agg1t[N_NODES * 128];
__device__ __half g_z1s[N_NODES * 128];      // fp16 z1 (halved gather traffic)
__device__ __half g_z1t[N_NODES * 128];
__device__ float g_z2s[N_NODES * 64];
__device__ float g_z2t[N_NODES * 64];
__device__ __half g_pwh[2][4][128 * 128];    // prepared weights [branch][layer][n][k], hi
__device__ __half g_pwl[2][4][128 * 128];    // lo residual
__device__ int g_deg[N_NODES];
__device__ int g_cursor[N_NODES];
__device__ int g_rowptr[N_NODES + 1];
__device__ int g_csrsrc[N_EDGES];
__device__ int g_bsum[128];
__device__ int g_boff[128];
__device__ int g_scan_ctr;

__device__ __forceinline__ int rowptr_at(int i) {
    return g_rowptr[i] + g_boff[i >> 10];
}

__device__ __forceinline__ void fp16_split(float v, __half& h, __half& l) {
    h = __float2half(v);
    l = __float2half(v - __half2float(h));
}

// fp16 tensor-core MMA, fp32 accumulate (family-portable, sm_80+)
__device__ __forceinline__ void mma16816(float* d, const uint32_t* a, const uint32_t* b) {
    asm volatile(
        "mma.sync.aligned.m16n8k16.row.col.f32.f16.f16.f32 "
        "{%0,%1,%2,%3}, {%4,%5,%6,%7}, {%8,%9}, {%0,%1,%2,%3};\n"
        : "+f"(d[0]), "+f"(d[1]), "+f"(d[2]), "+f"(d[3])
        : "r"(a[0]), "r"(a[1]), "r"(a[2]), "r"(a[3]), "r"(b[0]), "r"(b[1]));
}
#define LDSM4(r0, r1, r2, r3, addr) \
    asm volatile("ldmatrix.sync.aligned.m8n8.x4.shared.b16 {%0,%1,%2,%3}, [%4];" \
        : "=r"(r0), "=r"(r1), "=r"(r2), "=r"(r3) : "r"(addr))

__device__ __forceinline__ uint32_t smem_u32(const void* p) {
    uint32_t a;
    asm("{ .reg .u64 t; cvta.to.shared.u64 t, %1; cvt.u32.u64 %0, t; }" : "=r"(a) : "l"(p));
    return a;
}

// ======================= CSR build =======================
__global__ void hist_kernel(const int* __restrict__ ei) {
    if (blockIdx.x == 0 && threadIdx.x == 0) g_scan_ctr = 0;
    int e = blockIdx.x * blockDim.x + threadIdx.x;
    if (e < N_EDGES) atomicAdd(&g_deg[ei[N_EDGES + e]], 1);
}

__global__ void scan_kernel() {
    __shared__ int sm[1024];
    __shared__ int isLast;
    int t = threadIdx.x;
    int idx = blockIdx.x * 1024 + t;
    int d = (idx < N_NODES) ? g_deg[idx] : 0;
    sm[t] = d;
    __syncthreads();
    #pragma unroll
    for (int off = 1; off < 1024; off <<= 1) {
        int v = (t >= off) ? sm[t - off] : 0;
        __syncthreads();
        sm[t] += v;
        __syncthreads();
    }
    if (idx < N_NODES) g_rowptr[idx] = sm[t] - d;
    if (t == 1023) g_bsum[blockIdx.x] = sm[1023];
    __threadfence();
    if (t == 0) {
        int done = atomicAdd(&g_scan_ctr, 1);
        isLast = (done == (int)gridDim.x - 1);
    }
    __syncthreads();
    if (!isLast) return;
    int nb = gridDim.x;
    int v = (t < nb) ? ((volatile int*)g_bsum)[t] : 0;
    sm[t] = (t < 128) ? v : 0;
    __syncthreads();
    #pragma unroll
    for (int off = 1; off < 128; off <<= 1) {
        int u = (t >= off && t < 128) ? sm[t - off] : 0;
        __syncthreads();
        if (t < 128) sm[t] += u;
        __syncthreads();
    }
    if (t < nb) g_boff[t] = sm[t] - v;
    if (t == (N_NODES >> 10)) g_rowptr[N_NODES] = N_EDGES - (sm[t] - v);
}

__global__ void fill_kernel(const int* __restrict__ ei) {
    int e = blockIdx.x * blockDim.x + threadIdx.x;
    if (e < N_EDGES) {
        int src = ei[e];
        int dst = ei[N_EDGES + e];
        int pos = rowptr_at(dst) + atomicAdd(&g_cursor[dst], 1);
        g_csrsrc[pos] = src;
    }
}

// ======================= weight prep: coalesced smem transpose =======================
// grid (4, 8), block (32, 32). Reads coalesced over n; writes coalesced over k.
__global__ void prep_all_kernel(
    const float* w0, const float* w1, const float* w2, const float* w3,
    const float* w4, const float* w5, const float* w6, const float* w7)
{
    const int KREAL[4] = { IN_F, 128, 128, 128 };
    const int KSM[4]   = { 32, 128, 128, 128 };
    const int NOUT[4]  = { 128, 128, 128, 64 };
    const float* Ws[8] = { w0, w1, w2, w3, w4, w5, w6, w7 };
    __shared__ float tile[32][33];
    int y = blockIdx.y;
    int br = y >> 2, li = y & 3;
    int n0 = blockIdx.x * 32;
    if (n0 >= NOUT[li]) return;
    const float* W = Ws[y];
    int tx = threadIdx.x, ty = threadIdx.y;
    for (int k0 = 0; k0 < KSM[li]; k0 += 32) {
        int k = k0 + ty, n = n0 + tx;
        float v = 0.f;
        if (k < KREAL[li]) v = W[k * NOUT[li] + n];
        tile[ty][tx] = v;
        __syncthreads();
        float u = tile[tx][ty];
        __half h, l;
        fp16_split(u, h, l);
        int oidx = (n0 + ty) * KSM[li] + k0 + tx;
        g_pwh[br][li][oidx] = h;
        g_pwl[br][li][oidx] = l;
        __syncthreads();
    }
}

// ======================= layer-1 aggregation (index-batched) -> fp16 hi/lo, K pad 32
__global__ void agg0_kernel(const float* __restrict__ x) {
    int w = (blockIdx.x * blockDim.x + threadIdx.x) >> 5;
    int lane = threadIdx.x & 31;
    if (w >= N_NODES) return;
    float acc = (lane < IN_F) ? x[w * IN_F + lane] : 0.f;
    int s0 = rowptr_at(w), s1 = rowptr_at(w + 1);
    for (int e = s0; e < s1; ) {
        int cnt = s1 - e; if (cnt > 8) cnt = 8;
        int idx[8];
        #pragma unroll
        for (int j = 0; j < 8; j++) idx[j] = (j < cnt) ? g_csrsrc[e + j] : 0;
        float v[8];
        #pragma unroll
        for (int j = 0; j < 8; j++)
            v[j] = (j < cnt && lane < IN_F) ? x[idx[j] * IN_F + lane] : 0.f;
        #pragma unroll
        for (int j = 0; j < 8; j++) acc += v[j];
        e += cnt;
    }
    __half h, l;
    fp16_split(acc, h, l);
    g_agg0_h[w * 32 + lane] = h;
    g_agg0_l[w * 32 + lane] = l;
}

// ======================= layer-2 aggregation: warp per (node, branch), fp16 z1 gather
__global__ void agg1_kernel() {
    int br = blockIdx.y;
    const uint2* Z = (const uint2*)(br ? g_z1t : g_z1s);   // 4 halfs per lane
    int w = (blockIdx.x * blockDim.x + threadIdx.x) >> 5;
    int lane = threadIdx.x & 31;
    if (w >= N_NODES) return;
    float4 acc;
    {
        uint2 z = Z[(size_t)w * 32 + lane];
        float2 a = __half22float2(*(__half2*)&z.x);
        float2 b = __half22float2(*(__half2*)&z.y);
        acc = make_float4(a.x, a.y, b.x, b.y);
    }
    int s0 = rowptr_at(w), s1 = rowptr_at(w + 1);
    for (int e = s0; e < s1; ) {
        int cnt = s1 - e; if (cnt > 8) cnt = 8;
        int idx[8];
        #pragma unroll
        for (int j = 0; j < 8; j++) idx[j] = (j < cnt) ? g_csrsrc[e + j] : 0;
        uint2 v[8];
        #pragma unroll
        for (int j = 0; j < 8; j++)
            v[j] = (j < cnt) ? Z[(size_t)idx[j] * 32 + lane] : make_uint2(0u, 0u);
        #pragma unroll
        for (int j = 0; j < 8; j++) {
            float2 a = __half22float2(*(__half2*)&v[j].x);
            float2 b = __half22float2(*(__half2*)&v[j].y);
            acc.x += a.x; acc.y += a.y; acc.z += b.x; acc.w += b.y;
        }
        e += cnt;
    }
    __half2 p01 = __floats2half2_rn(acc.x, acc.y);
    __half2 p23 = __floats2half2_rn(acc.z, acc.w);
    __half* dst = br ? g_agg1t : g_agg1s;
    uint32_t* o = (uint32_t*)(dst + (size_t)w * 128 + lane * 4);
    o[0] = *(uint32_t*)&p01;
    o[1] = *(uint32_t*)&p23;
}

// ======================= W chunk loader: 64-col chunk, XOR-swizzled, pitch 64 halfs
__device__ __forceinline__ void load_w_chunk(
    __half* WH, __half* WL,
    const __half* __restrict__ Wh, const __half* __restrict__ Wl,
    int rows, int KS, int kk, int tid)
{
    for (int i = tid; i < rows * 8; i += 256) {
        int r = i >> 3, g = i & 7;
        int col = kk * 64 + g * 8;
        float4 vh = make_float4(0.f, 0.f, 0.f, 0.f), vl = vh;
        if (col < KS) {
            vh = *(const float4*)(Wh + r * KS + col);
            vl = *(const float4*)(Wl + r * KS + col);
        }
        int dst = r * 64 + ((g ^ (r & 7)) << 3);
        *(float4*)(WH + dst) = vh;
        *(float4*)(WL + dst) = vl;
    }
}

// ======================= fused 2-layer MLP, M-tile 64, 3 CTA/SM =======================
// ASPLIT=1 (layer 1): pass1 A split hi/lo -> 3 MMAs (exact GEMM1); K1=32.
// ASPLIT=0 (layer 2): pass1 A single fp16 -> 2 MMAs; K1=128.
// pass2 (both): H single fp16, W2 split -> 2 MMAs.
// Z1OUT: write output as fp16 (layer 1) vs fp32 (layer 2).
template<int K1, int NT2, int ASPLIT>
__global__ __launch_bounds__(256, 3) void mlp_kernel(
    const float* __restrict__ B1a, const float* __restrict__ B1b,
    const float* __restrict__ B2a, const float* __restrict__ B2b)
{
    constexpr int NOUT2 = NT2 * 32;
    constexpr int GA = K1 / 8;
    constexpr int KCH1 = (K1 + 63) / 64;
    constexpr int KS1 = K1 / 16;
    extern __shared__ char smraw[];
    __half* AS = (__half*)smraw;                          // 64x128 halfs
    __half* AL = AS + 64 * 128;                           // (ASPLIT) 64x128 halfs
    __half* WH = AL + (ASPLIT ? 64 * 128 : 0);
    __half* WL = WH + 128 * 64;

    int tid = threadIdx.x, lane = tid & 31, wid = tid >> 5;
    int warpM = wid & 1, warpN = wid >> 1;
    int by = blockIdx.y;
    int row0 = blockIdx.x * 64;
    int lg = lane >> 2, lt = lane & 3;

    int l1 = (K1 == 32) ? 0 : 2;
    const __half* Ag  = (K1 == 32) ? g_agg0_h : (by ? g_agg1t : g_agg1s);
    const __half* Agl = g_agg0_l;    // only used when ASPLIT
    const __half* W1h = g_pwh[by][l1];
    const __half* W1l = g_pwl[by][l1];
    const __half* W2h = g_pwh[by][l1 + 1];
    const __half* W2l = g_pwl[by][l1 + 1];
    const float* B1 = by ? B1b : B1a;
    const float* B2 = by ? B2b : B2a;

    // ---- A tile load: XOR swizzle, pitch 128 halfs ----
    for (int i = tid; i < 64 * GA; i += 256) {
        int r = i / GA, g = i % GA;
        int col = g * 8;
        int gr = row0 + r;
        float4 v = make_float4(0.f, 0.f, 0.f, 0.f);
        if (gr < N_NODES) v = *(const float4*)(Ag + (size_t)gr * K1 + col);
        int dst = r * 128 + ((g ^ (r & 7)) << 3);
        *(float4*)(AS + dst) = v;
        if (ASPLIT) {
            float4 vl = make_float4(0.f, 0.f, 0.f, 0.f);
            if (gr < N_NODES) vl = *(const float4*)(Agl + (size_t)gr * K1 + col);
            *(float4*)(AL + dst) = vl;
        }
    }
    load_w_chunk(WH, WL, W1h, W1l, 128, K1, 0, tid);
    __syncthreads();

    int a_row = lane & 15;
    int xA = lane & 7;
    int g0A = lane >> 4;
    int b_row = (lane & 7) + ((lane >> 4) & 1) * 8;
    int xW = b_row & 7;
    int g0W = (lane >> 3) & 1;

    uint32_t uAS = smem_u32(AS), uAL = smem_u32(AL);
    uint32_t uWH = smem_u32(WH), uWL = smem_u32(WL);

    uint32_t aRB[2], aRBL[2];
    #pragma unroll
    for (int tm = 0; tm < 2; tm++) {
        int R = warpM * 32 + tm * 16;
        aRB[tm] = uAS + (R + a_row) * 256;
        aRBL[tm] = uAL + (R + a_row) * 256;
    }

    // ---- pass 1: 64 x 128, warp tile 32 x 32 ----
    float acc[2][4][4];
    #pragma unroll
    for (int tm = 0; tm < 2; tm++)
        #pragma unroll
        for (int tn = 0; tn < 4; tn++)
            #pragma unroll
            for (int q = 0; q < 4; q++) acc[tm][tn][q] = 0.f;

    {
        uint32_t wRB_H[2], wRB_L[2];
        #pragma unroll
        for (int pp = 0; pp < 2; pp++) {
            int N0 = warpN * 32 + pp * 16;
            wRB_H[pp] = uWH + (N0 + b_row) * 128;
            wRB_L[pp] = uWL + (N0 + b_row) * 128;
        }
        constexpr int NKS = (KCH1 == 1) ? KS1 : 4;
        #pragma unroll
        for (int kk = 0; kk < KCH1; kk++) {
            if (kk > 0) {
                __syncthreads();
                load_w_chunk(WH, WL, W1h, W1l, 128, K1, kk, tid);
                __syncthreads();
            }
            #pragma unroll
            for (int ks = 0; ks < NKS; ks++) {
                int gs = kk * 4 + ks;
                uint32_t ao = (uint32_t)(((gs * 2 + g0A) ^ xA) << 4);
                uint32_t wo = (uint32_t)(((ks * 2 + g0W) ^ xW) << 4);
                uint32_t a[2][4], al[2][4];
                #pragma unroll
                for (int tm = 0; tm < 2; tm++) {
                    LDSM4(a[tm][0], a[tm][1], a[tm][2], a[tm][3], aRB[tm] + ao);
                    if (ASPLIT)
                        LDSM4(al[tm][0], al[tm][1], al[tm][2], al[tm][3], aRBL[tm] + ao);
                }
                #pragma unroll
                for (int pp = 0; pp < 2; pp++) {
                    uint32_t bh[4], bl[4];
                    LDSM4(bh[0], bh[1], bh[2], bh[3], wRB_H[pp] + wo);
                    LDSM4(bl[0], bl[1], bl[2], bl[3], wRB_L[pp] + wo);
                    #pragma unroll
                    for (int hf = 0; hf < 2; hf++) {
                        int tn = pp * 2 + hf;
                        #pragma unroll
                        for (int tm = 0; tm < 2; tm++) {
                            mma16816(acc[tm][tn], a[tm], bh + 2 * hf);
                            mma16816(acc[tm][tn], a[tm], bl + 2 * hf);
                            if (ASPLIT)
                                mma16816(acc[tm][tn], al[tm], bh + 2 * hf);
                        }
                    }
                }
            }
        }
    }
    __syncthreads();

    // ---- stage H = relu(acc + b1) -> A region (swizzled, fp16 single) ----
    #pragma unroll
    for (int tm = 0; tm < 2; tm++) {
        int m = warpM * 32 + tm * 16 + lg;
        #pragma unroll
        for (int tn = 0; tn < 4; tn++) {
            int n = warpN * 32 + tn * 8 + lt * 2;
            float2 bv = *(const float2*)(B1 + n);
            float v0 = fmaxf(acc[tm][tn][0] + bv.x, 0.f);
            float v1 = fmaxf(acc[tm][tn][1] + bv.y, 0.f);
            float v2 = fmaxf(acc[tm][tn][2] + bv.x, 0.f);
            float v3 = fmaxf(acc[tm][tn][3] + bv.y, 0.f);
            int off0 = m * 128 + (((n >> 3) ^ (m & 7)) << 3) + (n & 7);
            __half2 p0 = __floats2half2_rn(v0, v1);
            *(uint32_t*)(AS + off0) = *(uint32_t*)&p0;
            int off1 = (m + 8) * 128 + (((n >> 3) ^ (m & 7)) << 3) + (n & 7);
            __half2 p1 = __floats2half2_rn(v2, v3);
            *(uint32_t*)(AS + off1) = *(uint32_t*)&p1;
        }
    }
    load_w_chunk(WH, WL, W2h, W2l, NOUT2, 128, 0, tid);
    __syncthreads();

    // ---- pass 2: 64 x NOUT2, K = 128 ----
    float acc2[2][NT2][4];
    #pragma unroll
    for (int tm = 0; tm < 2; tm++)
        #pragma unroll
        for (int tn = 0; tn < NT2; tn++)
            #pragma unroll
            for (int q = 0; q < 4; q++) acc2[tm][tn][q] = 0.f;

    {
        uint32_t wRB_H[NT2 / 2], wRB_L[NT2 / 2];
        #pragma unroll
        for (int pp = 0; pp < NT2 / 2; pp++) {
            int N0 = warpN * (NOUT2 / 4) + pp * 16;
            wRB_H[pp] = uWH + (N0 + b_row) * 128;
            wRB_L[pp] = uWL + (N0 + b_row) * 128;
        }
        #pragma unroll
        for (int kk = 0; kk < 2; kk++) {
            if (kk > 0) {
                __syncthreads();
                load_w_chunk(WH, WL, W2h, W2l, NOUT2, 128, 1, tid);
                __syncthreads();
            }
            #pragma unroll
            for (int ks = 0; ks < 4; ks++) {
                int gs = kk * 4 + ks;
                uint32_t ao = (uint32_t)(((gs * 2 + g0A) ^ xA) << 4);
                uint32_t wo = (uint32_t)(((ks * 2 + g0W) ^ xW) << 4);
                uint32_t a[2][4];
                #pragma unroll
                for (int tm = 0; tm < 2; tm++)
                    LDSM4(a[tm][0], a[tm][1], a[tm][2], a[tm][3], aRB[tm] + ao);
                #pragma unroll
                for (int pp = 0; pp < NT2 / 2; pp++) {
                    uint32_t bh[4], bl[4];
                    LDSM4(bh[0], bh[1], bh[2], bh[3], wRB_H[pp] + wo);
                    LDSM4(bl[0], bl[1], bl[2], bl[3], wRB_L[pp] + wo);
                    #pragma unroll
                    for (int hf = 0; hf < 2; hf++) {
                        int tn = pp * 2 + hf;
                        #pragma unroll
                        for (int tm = 0; tm < 2; tm++) {
                            mma16816(acc2[tm][tn], a[tm], bh + 2 * hf);
                            mma16816(acc2[tm][tn], a[tm], bl + 2 * hf);
                        }
                    }
                }
            }
        }
    }

    // ---- epilogue: Z + b2 -> global (fp16 z1 for layer 1, fp32 z2 for layer 2) ----
    #pragma unroll
    for (int tm = 0; tm < 2; tm++) {
        int m = warpM * 32 + tm * 16 + lg;
        #pragma unroll
        for (int tn = 0; tn < NT2; tn++) {
            int n = warpN * (NOUT2 / 4) + tn * 8 + lt * 2;
            float2 bv = *(const float2*)(B2 + n);
            float o0x = acc2[tm][tn][0] + bv.x, o0y = acc2[tm][tn][1] + bv.y;
            float o1x = acc2[tm][tn][2] + bv.x, o1y = acc2[tm][tn][3] + bv.y;
            int g0 = row0 + m, g1 = row0 + m + 8;
            if (K1 == 32) {
                __half* z1 = by ? g_z1t : g_z1s;
                if (g0 < N_NODES) {
                    __half2 p = __floats2half2_rn(o0x, o0y);
                    *(uint32_t*)(z1 + (size_t)g0 * NOUT2 + n) = *(uint32_t*)&p;
                }
                if (g1 < N_NODES) {
                    __half2 p = __floats2half2_rn(o1x, o1y);
                    *(uint32_t*)(z1 + (size_t)g1 * NOUT2 + n) = *(uint32_t*)&p;
                }
            } else {
                float* z2 = by ? g_z2t : g_z2s;
                if (g0 < N_NODES) {
                    float2 o; o.x = o0x; o.y = o0y;
                    *(float2*)(z2 + (size_t)g0 * NOUT2 + n) = o;
                }
                if (g1 < N_NODES) {
                    float2 o; o.x = o1x; o.y = o1y;
                    *(float2*)(z2 + (size_t)g1 * NOUT2 + n) = o;
                }
            }
        }
    }
}

// ======================= per-graph 9x9 gram: 2 graphs per block =======================
__global__ void final_kernel(float* __restrict__ out) {
    __shared__ float zs[2][9 * 64];
    __shared__ float zt[2][9 * 64];
    int g0 = blockIdx.x * 2;
    int tid = threadIdx.x;
    const float4* ps = (const float4*)(g_z2s + (size_t)g0 * 9 * 64);
    const float4* pt = (const float4*)(g_z2t + (size_t)g0 * 9 * 64);
    for (int i = tid; i < 288; i += 256) {
        ((float4*)zs)[i] = ps[i];
        ((float4*)zt)[i] = pt[i];
    }
    __syncthreads();
    int gg = tid >> 7, t = tid & 127;
    if (t < 81) {
        int i = t / 9, j = t % 9;
        float acc = 0.f;
        #pragma unroll
        for (int k = 0; k < 64; k++) acc += zs[gg][i * 64 + k] * zt[gg][j * 64 + k];
        out[((g0 + gg) * 9 + i) * 9 + j] = acc;
    }
}

// ======================= launch =======================
extern "C" void kernel_launch(void* const* d_in, const int* in_sizes, int n_in,
                              void* d_out, int out_size) {
    const float* x  = (const float*)d_in[0];
    const int*   ei = (const int*)d_in[1];
    const float* B[2][4] = {
        { (const float*)d_in[3],  (const float*)d_in[5],  (const float*)d_in[7],  (const float*)d_in[9]  },
        { (const float*)d_in[11], (const float*)d_in[13], (const float*)d_in[15], (const float*)d_in[17] }
    };
    float* out = (float*)d_out;

    const int SMEM1 = (64 * 128 * 2 + 2 * 128 * 64) * 2;   // 65536 B (A hi+lo) -> 3 CTA/SM
    const int SMEM2 = (64 * 128 + 2 * 128 * 64) * 2;       // 49152 B -> 3 CTA/SM
    cudaFuncSetAttribute(mlp_kernel<32, 4, 1>,  cudaFuncAttributeMaxDynamicSharedMemorySize, SMEM1);
    cudaFuncSetAttribute(mlp_kernel<128, 2, 0>, cudaFuncAttributeMaxDynamicSharedMemorySize, SMEM2);

    const int GEMM_BLOCKS = (N_NODES + 63) / 64;         // 1407
    const int WARP_BLOCKS = (N_NODES * 32 + 255) / 256;
    const int SCAN_BLOCKS = (N_NODES + 1023) / 1024;     // 88

    // zero deg/cursor via memset nodes (capture-legal, full BW)
    void *p_deg = nullptr, *p_cur = nullptr;
    cudaGetSymbolAddress(&p_deg, g_deg);
    cudaGetSymbolAddress(&p_cur, g_cursor);
    cudaMemsetAsync(p_deg, 0, N_NODES * sizeof(int));
    cudaMemsetAsync(p_cur, 0, N_NODES * sizeof(int));

    // CSR build (single-pass scan)
    hist_kernel<<<(N_EDGES + 255) / 256, 256>>>(ei);
    scan_kernel<<<SCAN_BLOCKS, 1024>>>();
    fill_kernel<<<(N_EDGES + 255) / 256, 256>>>(ei);

    // weight prep (single launch, coalesced transpose)
    prep_all_kernel<<<dim3(4, 8), dim3(32, 32)>>>(
        (const float*)d_in[2],  (const float*)d_in[4],  (const float*)d_in[6],  (const float*)d_in[8],
        (const float*)d_in[10], (const float*)d_in[12], (const float*)d_in[14], (const float*)d_in[16]);

    agg0_kernel<<<WARP_BLOCKS, 256>>>(x);

    // GIN layer 1 (fused MLP, GEMM1 exact 3-term), both branches in one launch
    mlp_kernel<32, 4, 1><<<dim3(GEMM_BLOCKS, 2), 256, SMEM1>>>(B[0][0], B[1][0], B[0][1], B[1][1]);

    // layer 2 aggregation: warp per (node, branch), fp16 gather
    agg1_kernel<<<dim3(WARP_BLOCKS, 2), 256>>>();

    // GIN layer 2 (fused MLP), both branches in one launch
    mlp_kernel<128, 2, 0><<<dim3(GEMM_BLOCKS, 2), 256, SMEM2>>>(B[0][2], B[1][2], B[0][3], B[1][3]);

    final_kernel<<<(N_GRAPH + 1) / 2, 256>>>(out);
}

// round 15
// speedup vs baseline: 1.5711x; 1.0073x over previous
#include <cuda_runtime.h>
#include <cuda_fp16.h>
#include <cstdint>

#define N_NODES 90000
#define N_EDGES 540000
#define IN_F    30
#define N_GRAPH 10000

// ======================= global scratch =======================
__device__ __half g_agg0_h[N_NODES * 32];
__device__ __half g_agg0_l[N_NODES * 32];
__device__ __half g_agg1s[N_NODES * 128];
__device__ __half g_agg1t[N_NODES * 128];
__device__ __half g_z1s[N_NODES * 128];      // fp16 z1 (halved gather traffic)
__device__ __half g_z1t[N_NODES * 128];
__device__ float g_z2s[N_NODES * 64];
__device__ float g_z2t[N_NODES * 64];
__device__ __half g_pwh[2][4][128 * 128];    // prepared weights [branch][layer][n][k], hi
__device__ __half g_pwl[2][4][128 * 128];    // lo residual
__device__ int g_deg[N_NODES];
__device__ int g_cursor[N_NODES];
__device__ int g_rowptr[N_NODES + 1];
__device__ int g_csrsrc[N_EDGES];
__device__ int g_bsum[128];
__device__ int g_boff[128];
__device__ int g_scan_ctr;

__device__ __forceinline__ int rowptr_at(int i) {
    return g_rowptr[i] + g_boff[i >> 10];
}

__device__ __forceinline__ void fp16_split(float v, __half& h, __half& l) {
    h = __float2half(v);
    l = __float2half(v - __half2float(h));
}

// fp16 tensor-core MMA, fp32 accumulate (family-portable, sm_80+)
__device__ __forceinline__ void mma16816(float* d, const uint32_t* a, const uint32_t* b) {
    asm volatile(
        "mma.sync.aligned.m16n8k16.row.col.f32.f16.f16.f32 "
        "{%0,%1,%2,%3}, {%4,%5,%6,%7}, {%8,%9}, {%0,%1,%2,%3};\n"
        : "+f"(d[0]), "+f"(d[1]), "+f"(d[2]), "+f"(d[3])
        : "r"(a[0]), "r"(a[1]), "r"(a[2]), "r"(a[3]), "r"(b[0]), "r"(b[1]));
}
#define LDSM4(r0, r1, r2, r3, addr) \
    asm volatile("ldmatrix.sync.aligned.m8n8.x4.shared.b16 {%0,%1,%2,%3}, [%4];" \
        : "=r"(r0), "=r"(r1), "=r"(r2), "=r"(r3) : "r"(addr))

__device__ __forceinline__ uint32_t smem_u32(const void* p) {
    uint32_t a;
    asm("{ .reg .u64 t; cvta.to.shared.u64 t, %1; cvt.u32.u64 %0, t; }" : "=r"(a) : "l"(p));
    return a;
}

// ======================= CSR build =======================
__global__ void hist_kernel(const int* __restrict__ ei) {
    if (blockIdx.x == 0 && threadIdx.x == 0) g_scan_ctr = 0;
    int e = blockIdx.x * blockDim.x + threadIdx.x;
    if (e < N_EDGES) atomicAdd(&g_deg[ei[N_EDGES + e]], 1);
}

// single-pass scan: warp-shuffle phase 1, smem phase 2 in last block
__global__ void scan_kernel() {
    __shared__ int wsum[32];
    __shared__ int sm2[128];
    __shared__ int isLast;
    int t = threadIdx.x, lane = t & 31, wrp = t >> 5;
    int idx = blockIdx.x * 1024 + t;
    int d = (idx < N_NODES) ? g_deg[idx] : 0;
    int v = d;
    #pragma unroll
    for (int off = 1; off < 32; off <<= 1) {
        int u = __shfl_up_sync(0xffffffffu, v, off);
        if (lane >= off) v += u;
    }
    if (lane == 31) wsum[wrp] = v;
    __syncthreads();
    if (wrp == 0) {
        int s = wsum[lane];
        #pragma unroll
        for (int off = 1; off < 32; off <<= 1) {
            int u = __shfl_up_sync(0xffffffffu, s, off);
            if (lane >= off) s += u;
        }
        wsum[lane] = s;   // inclusive prefix of warp sums
    }
    __syncthreads();
    int incl = ((wrp > 0) ? wsum[wrp - 1] : 0) + v;
    if (idx < N_NODES) g_rowptr[idx] = incl - d;   // block-local exclusive
    if (t == 1023) g_bsum[blockIdx.x] = incl;
    __threadfence();
    if (t == 0) {
        int done = atomicAdd(&g_scan_ctr, 1);
        isLast = (done == (int)gridDim.x - 1);
    }
    __syncthreads();
    if (!isLast) return;
    // last block: scan the 88 block sums (proven smem path, all threads participate)
    int nb = gridDim.x;
    int bv = (t < nb) ? ((volatile int*)g_bsum)[t] : 0;
    if (t < 128) sm2[t] = bv;
    __syncthreads();
    #pragma unroll
    for (int off = 1; off < 128; off <<= 1) {
        int u = (t >= off && t < 128) ? sm2[t - off] : 0;
        __syncthreads();
        if (t < 128) sm2[t] += u;
        __syncthreads();
    }
    if (t < nb) g_boff[t] = sm2[t] - bv;
    if (t == (N_NODES >> 10)) g_rowptr[N_NODES] = N_EDGES - (sm2[t] - bv);
}

__global__ void fill_kernel(const int* __restrict__ ei) {
    int e = blockIdx.x * blockDim.x + threadIdx.x;
    if (e < N_EDGES) {
        int src = ei[e];
        int dst = ei[N_EDGES + e];
        int pos = rowptr_at(dst) + atomicAdd(&g_cursor[dst], 1);
        g_csrsrc[pos] = src;
    }
}

// ======================= weight prep: coalesced transpose, K-chunk parallel =======================
// grid (4, 8, 4), block (32, 32). blockIdx.z selects a 32-wide K chunk.
__global__ void prep_all_kernel(
    const float* w0, const float* w1, const float* w2, const float* w3,
    const float* w4, const float* w5, const float* w6, const float* w7)
{
    const int KREAL[4] = { IN_F, 128, 128, 128 };
    const int KSM[4]   = { 32, 128, 128, 128 };
    const int NOUT[4]  = { 128, 128, 128, 64 };
    const float* Ws[8] = { w0, w1, w2, w3, w4, w5, w6, w7 };
    __shared__ float tile[32][33];
    int y = blockIdx.y;
    int br = y >> 2, li = y & 3;
    int n0 = blockIdx.x * 32;
    int k0 = blockIdx.z * 32;
    if (n0 >= NOUT[li] || k0 >= KSM[li]) return;
    const float* W = Ws[y];
    int tx = threadIdx.x, ty = threadIdx.y;
    int k = k0 + ty, n = n0 + tx;
    float v = 0.f;
    if (k < KREAL[li]) v = W[k * NOUT[li] + n];
    tile[ty][tx] = v;
    __syncthreads();
    float u = tile[tx][ty];
    __half h, l;
    fp16_split(u, h, l);
    int oidx = (n0 + ty) * KSM[li] + k0 + tx;
    g_pwh[br][li][oidx] = h;
    g_pwl[br][li][oidx] = l;
}

// ======================= layer-1 aggregation (index-batched) -> fp16 hi/lo, K pad 32
__global__ void agg0_kernel(const float* __restrict__ x) {
    int w = (blockIdx.x * blockDim.x + threadIdx.x) >> 5;
    int lane = threadIdx.x & 31;
    if (w >= N_NODES) return;
    float acc = (lane < IN_F) ? x[w * IN_F + lane] : 0.f;
    int s0 = rowptr_at(w), s1 = rowptr_at(w + 1);
    for (int e = s0; e < s1; ) {
        int cnt = s1 - e; if (cnt > 8) cnt = 8;
        int idx[8];
        #pragma unroll
        for (int j = 0; j < 8; j++) idx[j] = (j < cnt) ? g_csrsrc[e + j] : 0;
        float v[8];
        #pragma unroll
        for (int j = 0; j < 8; j++)
            v[j] = (j < cnt && lane < IN_F) ? x[idx[j] * IN_F + lane] : 0.f;
        #pragma unroll
        for (int j = 0; j < 8; j++) acc += v[j];
        e += cnt;
    }
    __half h, l;
    fp16_split(acc, h, l);
    g_agg0_h[w * 32 + lane] = h;
    g_agg0_l[w * 32 + lane] = l;
}

// ======================= layer-2 aggregation: warp per (node, branch), fp16 z1 gather
__global__ void agg1_kernel() {
    int br = blockIdx.y;
    const uint2* Z = (const uint2*)(br ? g_z1t : g_z1s);
    int w = (blockIdx.x * blockDim.x + threadIdx.x) >> 5;
    int lane = threadIdx.x & 31;
    if (w >= N_NODES) return;
    float4 acc;
    {
        uint2 z = Z[(size_t)w * 32 + lane];
        float2 a = __half22float2(*(__half2*)&z.x);
        float2 b = __half22float2(*(__half2*)&z.y);
        acc = make_float4(a.x, a.y, b.x, b.y);
    }
    int s0 = rowptr_at(w), s1 = rowptr_at(w + 1);
    for (int e = s0; e < s1; ) {
        int cnt = s1 - e; if (cnt > 8) cnt = 8;
        int idx[8];
        #pragma unroll
        for (int j = 0; j < 8; j++) idx[j] = (j < cnt) ? g_csrsrc[e + j] : 0;
        uint2 v[8];
        #pragma unroll
        for (int j = 0; j < 8; j++)
            v[j] = (j < cnt) ? Z[(size_t)idx[j] * 32 + lane] : make_uint2(0u, 0u);
        #pragma unroll
        for (int j = 0; j < 8; j++) {
            float2 a = __half22float2(*(__half2*)&v[j].x);
            float2 b = __half22float2(*(__half2*)&v[j].y);
            acc.x += a.x; acc.y += a.y; acc.z += b.x; acc.w += b.y;
        }
        e += cnt;
    }
    __half2 p01 = __floats2half2_rn(acc.x, acc.y);
    __half2 p23 = __floats2half2_rn(acc.z, acc.w);
    __half* dst = br ? g_agg1t : g_agg1s;
    uint32_t* o = (uint32_t*)(dst + (size_t)w * 128 + lane * 4);
    o[0] = *(uint32_t*)&p01;
    o[1] = *(uint32_t*)&p23;
}

// ======================= W chunk loader: 64-col chunk, XOR-swizzled, pitch 64 halfs
__device__ __forceinline__ void load_w_chunk(
    __half* WH, __half* WL,
    const __half* __restrict__ Wh, const __half* __restrict__ Wl,
    int rows, int KS, int kk, int tid)
{
    for (int i = tid; i < rows * 8; i += 256) {
        int r = i >> 3, g = i & 7;
        int col = kk * 64 + g * 8;
        float4 vh = make_float4(0.f, 0.f, 0.f, 0.f), vl = vh;
        if (col < KS) {
            vh = *(const float4*)(Wh + r * KS + col);
            vl = *(const float4*)(Wl + r * KS + col);
        }
        int dst = r * 64 + ((g ^ (r & 7)) << 3);
        *(float4*)(WH + dst) = vh;
        *(float4*)(WL + dst) = vl;
    }
}

// ======================= fused 2-layer MLP, M-tile 64, 3 CTA/SM =======================
// ASPLIT=1 (layer 1, K1=32): A hi in granules 0-3 of AS, A lo packed in granules 8-11
//   (disjoint under XOR swizzle: bit3 of granule untouched by xA<8) -> 3 MMAs pass1.
// ASPLIT=0 (layer 2, K1=128): A single fp16 -> 2 MMAs.
// pass2 (both): H single fp16 in AS, W2 split -> 2 MMAs. smem = 48 KB both.
template<int K1, int NT2, int ASPLIT>
__global__ __launch_bounds__(256, 3) void mlp_kernel(
    const float* __restrict__ B1a, const float* __restrict__ B1b,
    const float* __restrict__ B2a, const float* __restrict__ B2b)
{
    constexpr int NOUT2 = NT2 * 32;
    constexpr int GA = K1 / 8;
    constexpr int KCH1 = (K1 + 63) / 64;
    constexpr int KS1 = K1 / 16;
    extern __shared__ char smraw[];
    __half* AS = (__half*)smraw;          // 64x128 halfs (16 KB)
    __half* WH = AS + 64 * 128;           // 128x64 halfs
    __half* WL = WH + 128 * 64;

    int tid = threadIdx.x, lane = tid & 31, wid = tid >> 5;
    int warpM = wid & 1, warpN = wid >> 1;
    int by = blockIdx.y;
    int row0 = blockIdx.x * 64;
    int lg = lane >> 2, lt = lane & 3;

    int l1 = (K1 == 32) ? 0 : 2;
    const __half* Ag  = (K1 == 32) ? g_agg0_h : (by ? g_agg1t : g_agg1s);
    const __half* Agl = g_agg0_l;    // only used when ASPLIT
    const __half* W1h = g_pwh[by][l1];
    const __half* W1l = g_pwl[by][l1];
    const __half* W2h = g_pwh[by][l1 + 1];
    const __half* W2l = g_pwl[by][l1 + 1];
    const float* B1 = by ? B1b : B1a;
    const float* B2 = by ? B2b : B2a;

    // ---- A tile load: XOR swizzle, pitch 128 halfs; lo packed at +64 cols when ASPLIT ----
    for (int i = tid; i < 64 * GA; i += 256) {
        int r = i / GA, g = i % GA;
        int col = g * 8;
        int gr = row0 + r;
        float4 v = make_float4(0.f, 0.f, 0.f, 0.f);
        if (gr < N_NODES) v = *(const float4*)(Ag + (size_t)gr * K1 + col);
        int dst = r * 128 + ((g ^ (r & 7)) << 3);
        *(float4*)(AS + dst) = v;
        if (ASPLIT) {
            float4 vl = make_float4(0.f, 0.f, 0.f, 0.f);
            if (gr < N_NODES) vl = *(const float4*)(Agl + (size_t)gr * K1 + col);
            *(float4*)(AS + dst + 64) = vl;   // granule g+8 (bit3 clear in xA)
        }
    }
    load_w_chunk(WH, WL, W1h, W1l, 128, K1, 0, tid);
    __syncthreads();

    int a_row = lane & 15;
    int xA = lane & 7;
    int g0A = lane >> 4;
    int b_row = (lane & 7) + ((lane >> 4) & 1) * 8;
    int xW = b_row & 7;
    int g0W = (lane >> 3) & 1;

    uint32_t uAS = smem_u32(AS);
    uint32_t uWH = smem_u32(WH), uWL = smem_u32(WL);

    uint32_t aRB[2];
    #pragma unroll
    for (int tm = 0; tm < 2; tm++) {
        int R = warpM * 32 + tm * 16;
        aRB[tm] = uAS + (R + a_row) * 256;
    }

    // ---- pass 1: 64 x 128, warp tile 32 x 32 ----
    float acc[2][4][4];
    #pragma unroll
    for (int tm = 0; tm < 2; tm++)
        #pragma unroll
        for (int tn = 0; tn < 4; tn++)
            #pragma unroll
            for (int q = 0; q < 4; q++) acc[tm][tn][q] = 0.f;

    {
        uint32_t wRB_H[2], wRB_L[2];
        #pragma unroll
        for (int pp = 0; pp < 2; pp++) {
            int N0 = warpN * 32 + pp * 16;
            wRB_H[pp] = uWH + (N0 + b_row) * 128;
            wRB_L[pp] = uWL + (N0 + b_row) * 128;
        }
        constexpr int NKS = (KCH1 == 1) ? KS1 : 4;
        #pragma unroll
        for (int kk = 0; kk < KCH1; kk++) {
            if (kk > 0) {
                __syncthreads();
                load_w_chunk(WH, WL, W1h, W1l, 128, K1, kk, tid);
                __syncthreads();
            }
            #pragma unroll
            for (int ks = 0; ks < NKS; ks++) {
                int gs = kk * 4 + ks;
                uint32_t ao = (uint32_t)(((gs * 2 + g0A) ^ xA) << 4);
                uint32_t wo = (uint32_t)(((ks * 2 + g0W) ^ xW) << 4);
                uint32_t a[2][4], al[2][4];
                #pragma unroll
                for (int tm = 0; tm < 2; tm++) {
                    LDSM4(a[tm][0], a[tm][1], a[tm][2], a[tm][3], aRB[tm] + ao);
                    if (ASPLIT)
                        LDSM4(al[tm][0], al[tm][1], al[tm][2], al[tm][3], aRB[tm] + ao + 128);
                }
                #pragma unroll
                for (int pp = 0; pp < 2; pp++) {
                    uint32_t bh[4], bl[4];
                    LDSM4(bh[0], bh[1], bh[2], bh[3], wRB_H[pp] + wo);
                    LDSM4(bl[0], bl[1], bl[2], bl[3], wRB_L[pp] + wo);
                    #pragma unroll
                    for (int hf = 0; hf < 2; hf++) {
                        int tn = pp * 2 + hf;
                        #pragma unroll
                        for (int tm = 0; tm < 2; tm++) {
                            mma16816(acc[tm][tn], a[tm], bh + 2 * hf);
                            mma16816(acc[tm][tn], a[tm], bl + 2 * hf);
                            if (ASPLIT)
                                mma16816(acc[tm][tn], al[tm], bh + 2 * hf);
                        }
                    }
                }
            }
        }
    }
    __syncthreads();

    // ---- stage H = relu(acc + b1) -> AS (swizzled, fp16 single) ----
    #pragma unroll
    for (int tm = 0; tm < 2; tm++) {
        int m = warpM * 32 + tm * 16 + lg;
        #pragma unroll
        for (int tn = 0; tn < 4; tn++) {
            int n = warpN * 32 + tn * 8 + lt * 2;
            float2 bv = *(const float2*)(B1 + n);
            float v0 = fmaxf(acc[tm][tn][0] + bv.x, 0.f);
            float v1 = fmaxf(acc[tm][tn][1] + bv.y, 0.f);
            float v2 = fmaxf(acc[tm][tn][2] + bv.x, 0.f);
            float v3 = fmaxf(acc[tm][tn][3] + bv.y, 0.f);
            int off0 = m * 128 + (((n >> 3) ^ (m & 7)) << 3) + (n & 7);
            __half2 p0 = __floats2half2_rn(v0, v1);
            *(uint32_t*)(AS + off0) = *(uint32_t*)&p0;
            int off1 = (m + 8) * 128 + (((n >> 3) ^ (m & 7)) << 3) + (n & 7);
            __half2 p1 = __floats2half2_rn(v2, v3);
            *(uint32_t*)(AS + off1) = *(uint32_t*)&p1;
        }
    }
    load_w_chunk(WH, WL, W2h, W2l, NOUT2, 128, 0, tid);
    __syncthreads();

    // ---- pass 2: 64 x NOUT2, K = 128 ----
    float acc2[2][NT2][4];
    #pragma unroll
    for (int tm = 0; tm < 2; tm++)
        #pragma unroll
        for (int tn = 0; tn < NT2; tn++)
            #pragma unroll
            for (int q = 0; q < 4; q++) acc2[tm][tn][q] = 0.f;

    {
        uint32_t wRB_H[NT2 / 2], wRB_L[NT2 / 2];
        #pragma unroll
        for (int pp = 0; pp < NT2 / 2; pp++) {
            int N0 = warpN * (NOUT2 / 4) + pp * 16;
            wRB_H[pp] = uWH + (N0 + b_row) * 128;
            wRB_L[pp] = uWL + (N0 + b_row) * 128;
        }
        #pragma unroll
        for (int kk = 0; kk < 2; kk++) {
            if (kk > 0) {
                __syncthreads();
                load_w_chunk(WH, WL, W2h, W2l, NOUT2, 128, 1, tid);
                __syncthreads();
            }
            #pragma unroll
            for (int ks = 0; ks < 4; ks++) {
                int gs = kk * 4 + ks;
                uint32_t ao = (uint32_t)(((gs * 2 + g0A) ^ xA) << 4);
                uint32_t wo = (uint32_t)(((ks * 2 + g0W) ^ xW) << 4);
                uint32_t a[2][4];
                #pragma unroll
                for (int tm = 0; tm < 2; tm++)
                    LDSM4(a[tm][0], a[tm][1], a[tm][2], a[tm][3], aRB[tm] + ao);
                #pragma unroll
                for (int pp = 0; pp < NT2 / 2; pp++) {
                    uint32_t bh[4], bl[4];
                    LDSM4(bh[0], bh[1], bh[2], bh[3], wRB_H[pp] + wo);
                    LDSM4(bl[0], bl[1], bl[2], bl[3], wRB_L[pp] + wo);
                    #pragma unroll
                    for (int hf = 0; hf < 2; hf++) {
                        int tn = pp * 2 + hf;
                        #pragma unroll
                        for (int tm = 0; tm < 2; tm++) {
                            mma16816(acc2[tm][tn], a[tm], bh + 2 * hf);
                            mma16816(acc2[tm][tn], a[tm], bl + 2 * hf);
                        }
                    }
                }
            }
        }
    }

    // ---- epilogue: Z + b2 -> global (fp16 z1 for layer 1, fp32 z2 for layer 2) ----
    #pragma unroll
    for (int tm = 0; tm < 2; tm++) {
        int m = warpM * 32 + tm * 16 + lg;
        #pragma unroll
        for (int tn = 0; tn < NT2; tn++) {
            int n = warpN * (NOUT2 / 4) + tn * 8 + lt * 2;
            float2 bv = *(const float2*)(B2 + n);
            float o0x = acc2[tm][tn][0] + bv.x, o0y = acc2[tm][tn][1] + bv.y;
            float o1x = acc2[tm][tn][2] + bv.x, o1y = acc2[tm][tn][3] + bv.y;
            int g0 = row0 + m, g1 = row0 + m + 8;
            if (K1 == 32) {
                __half* z1 = by ? g_z1t : g_z1s;
                if (g0 < N_NODES) {
                    __half2 p = __floats2half2_rn(o0x, o0y);
                    *(uint32_t*)(z1 + (size_t)g0 * NOUT2 + n) = *(uint32_t*)&p;
                }
                if (g1 < N_NODES) {
                    __half2 p = __floats2half2_rn(o1x, o1y);
                    *(uint32_t*)(z1 + (size_t)g1 * NOUT2 + n) = *(uint32_t*)&p;
                }
            } else {
                float* z2 = by ? g_z2t : g_z2s;
                if (g0 < N_NODES) {
                    float2 o; o.x = o0x; o.y = o0y;
                    *(float2*)(z2 + (size_t)g0 * NOUT2 + n) = o;
                }
                if (g1 < N_NODES) {
                    float2 o; o.x = o1x; o.y = o1y;
                    *(float2*)(z2 + (size_t)g1 * NOUT2 + n) = o;
                }
            }
        }
    }
}

// ======================= per-graph 9x9 gram: 4 graphs per block =======================
__global__ void final_kernel(float* __restrict__ out) {
    __shared__ float zs[4][9 * 64];
    __shared__ float zt[4][9 * 64];
    int g0 = blockIdx.x * 4;
    int tid = threadIdx.x;
    const float4* ps = (const float4*)(g_z2s + (size_t)g0 * 9 * 64);
    const float4* pt = (const float4*)(g_z2t + (size_t)g0 * 9 * 64);
    for (int i = tid; i < 576; i += 512) {
        ((float4*)zs)[i] = ps[i];
        ((float4*)zt)[i] = pt[i];
    }
    __syncthreads();
    int gg = tid >> 7, t = tid & 127;
    if (t < 81) {
        int i = t / 9, j = t % 9;
        float acc = 0.f;
        #pragma unroll
        for (int k = 0; k < 64; k++) acc += zs[gg][i * 64 + k] * zt[gg][j * 64 + k];
        out[((g0 + gg) * 9 + i) * 9 + j] = acc;
    }
}

// ======================= launch =======================
extern "C" void kernel_launch(void* const* d_in, const int* in_sizes, int n_in,
                              void* d_out, int out_size) {
    const float* x  = (const float*)d_in[0];
    const int*   ei = (const int*)d_in[1];
    const float* B[2][4] = {
        { (const float*)d_in[3],  (const float*)d_in[5],  (const float*)d_in[7],  (const float*)d_in[9]  },
        { (const float*)d_in[11], (const float*)d_in[13], (const float*)d_in[15], (const float*)d_in[17] }
    };
    float* out = (float*)d_out;

    const int SMEM = (64 * 128 + 2 * 128 * 64) * 2;   // 49152 B -> 3 CTA/SM (4 if regs allow)
    cudaFuncSetAttribute(mlp_kernel<32, 4, 1>,  cudaFuncAttributeMaxDynamicSharedMemorySize, SMEM);
    cudaFuncSetAttribute(mlp_kernel<128, 2, 0>, cudaFuncAttributeMaxDynamicSharedMemorySize, SMEM);

    const int GEMM_BLOCKS = (N_NODES + 63) / 64;         // 1407
    const int WARP_BLOCKS = (N_NODES * 32 + 255) / 256;
    const int SCAN_BLOCKS = (N_NODES + 1023) / 1024;     // 88

    // zero deg/cursor via memset nodes (capture-legal, full BW)
    void *p_deg = nullptr, *p_cur = nullptr;
    cudaGetSymbolAddress(&p_deg, g_deg);
    cudaGetSymbolAddress(&p_cur, g_cursor);
    cudaMemsetAsync(p_deg, 0, N_NODES * sizeof(int));
    cudaMemsetAsync(p_cur, 0, N_NODES * sizeof(int));

    // CSR build (single-pass scan)
    hist_kernel<<<(N_EDGES + 255) / 256, 256>>>(ei);
    scan_kernel<<<SCAN_BLOCKS, 1024>>>();
    fill_kernel<<<(N_EDGES + 255) / 256, 256>>>(ei);

    // weight prep (single launch, coalesced transpose, K-chunk parallel)
    prep_all_kernel<<<dim3(4, 8, 4), dim3(32, 32)>>>(
        (const float*)d_in[2],  (const float*)d_in[4],  (const float*)d_in[6],  (const float*)d_in[8],
        (const float*)d_in[10], (const float*)d_in[12], (const float*)d_in[14], (const float*)d_in[16]);

    agg0_kernel<<<WARP_BLOCKS, 256>>>(x);

    // GIN layer 1 (fused MLP, GEMM1 exact 3-term), both branches in one launch
    mlp_kernel<32, 4, 1><<<dim3(GEMM_BLOCKS, 2), 256, SMEM>>>(B[0][0], B[1][0], B[0][1], B[1][1]);

    // layer 2 aggregation: warp per (node, branch), fp16 gather
    agg1_kernel<<<dim3(WARP_BLOCKS, 2), 256>>>();

    // GIN layer 2 (fused MLP), both branches in one launch
    mlp_kernel<128, 2, 0><<<dim3(GEMM_BLOCKS, 2), 256, SMEM>>>(B[0][2], B[1][2], B[0][3], B[1][3]);

    final_kernel<<<(N_GRAPH + 3) / 4, 512>>>(out);
}

// round 16
// speedup vs baseline: 1.5824x; 1.0072x over previous
#include <cuda_runtime.h>
#include <cuda_fp16.h>
#include <cstdint>

#define N_NODES 90000
#define N_EDGES 540000
#define IN_F    30
#define N_GRAPH 10000
#define HIST_BLOCKS ((N_EDGES + 255) / 256)   // 2110
#define PREP_BLOCKS 128

// ======================= global scratch =======================
__device__ __half g_agg0_h[N_NODES * 32];
__device__ __half g_agg0_l[N_NODES * 32];
__device__ __half g_agg1s[N_NODES * 128];
__device__ __half g_agg1t[N_NODES * 128];
__device__ __half g_z1s[N_NODES * 128];      // fp16 z1 (halved gather traffic)
__device__ __half g_z1t[N_NODES * 128];
__device__ float g_z2s[N_NODES * 64];
__device__ float g_z2t[N_NODES * 64];
__device__ __half g_pwh[2][4][128 * 128];    // prepared weights [branch][layer][n][k], hi
__device__ __half g_pwl[2][4][128 * 128];    // lo residual
__device__ int g_deg[N_NODES];
__device__ int g_rowptr[N_NODES + 1];
__device__ int g_csrsrc[N_EDGES];
__device__ int g_bsum[128];
__device__ int g_boff[128];
__device__ int g_scan_ctr;

__device__ __forceinline__ int rowptr_at(int i) {
    return g_rowptr[i] + g_boff[i >> 10];
}

__device__ __forceinline__ void fp16_split(float v, __half& h, __half& l) {
    h = __float2half(v);
    l = __float2half(v - __half2float(h));
}

// fp16 tensor-core MMA, fp32 accumulate (family-portable, sm_80+)
__device__ __forceinline__ void mma16816(float* d, const uint32_t* a, const uint32_t* b) {
    asm volatile(
        "mma.sync.aligned.m16n8k16.row.col.f32.f16.f16.f32 "
        "{%0,%1,%2,%3}, {%4,%5,%6,%7}, {%8,%9}, {%0,%1,%2,%3};\n"
        : "+f"(d[0]), "+f"(d[1]), "+f"(d[2]), "+f"(d[3])
        : "r"(a[0]), "r"(a[1]), "r"(a[2]), "r"(a[3]), "r"(b[0]), "r"(b[1]));
}
#define LDSM4(r0, r1, r2, r3, addr) \
    asm volatile("ldmatrix.sync.aligned.m8n8.x4.shared.b16 {%0,%1,%2,%3}, [%4];" \
        : "=r"(r0), "=r"(r1), "=r"(r2), "=r"(r3) : "r"(addr))

__device__ __forceinline__ uint32_t smem_u32(const void* p) {
    uint32_t a;
    asm("{ .reg .u64 t; cvta.to.shared.u64 t, %1; cvt.u32.u64 %0, t; }" : "=r"(a) : "l"(p));
    return a;
}

// ======================= fused histogram + weight prep =======================
// blocks [0, HIST_BLOCKS): edge histogram. blocks [HIST_BLOCKS, +PREP_BLOCKS): weight prep.
// Weight y (br = y>>2, li = y&3): out layout [n][k], KSM x NOUT elems, flat idx = n*KSM + k.
__global__ void hist_prep_kernel(const int* __restrict__ ei,
    const float* w0, const float* w1, const float* w2, const float* w3,
    const float* w4, const float* w5, const float* w6, const float* w7)
{
    int b = blockIdx.x;
    if (b < HIST_BLOCKS) {
        if (b == 0 && threadIdx.x == 0) g_scan_ctr = 0;
        int e = b * 256 + threadIdx.x;
        if (e < N_EDGES) atomicAdd(&g_deg[ei[N_EDGES + e]], 1);
        return;
    }
    // ---- prep portion ----
    const int KREAL[4] = { IN_F, 128, 128, 128 };
    const int KSM[4]   = { 32, 128, 128, 128 };
    const int NOUT[4]  = { 128, 128, 128, 64 };
    const int SIZE[4]  = { 4096, 16384, 16384, 8192 };        // KSM*NOUT
    const int CUM[9]   = { 0, 4096, 20480, 36864, 45056,
                           49152, 65536, 81920, 90112 };
    const float* Ws[8] = { w0, w1, w2, w3, w4, w5, w6, w7 };
    const int TOTAL = 90112;
    int pb = b - HIST_BLOCKS;
    for (int idx = pb * 256 + threadIdx.x; idx < TOTAL; idx += PREP_BLOCKS * 256) {
        int y = 0;
        #pragma unroll
        for (int j = 1; j < 8; j++) if (idx >= CUM[j]) y = j;
        int li = y & 3, br = y >> 2;
        int il = idx - CUM[y];
        int n = il / KSM[li], k = il - n * KSM[li];
        float v = (k < KREAL[li]) ? Ws[y][k * NOUT[li] + n] : 0.f;
        __half h, l;
        fp16_split(v, h, l);
        g_pwh[br][li][il] = h;
        g_pwl[br][li][il] = l;
    }
    (void)SIZE;
}

// ======================= single-pass scan: warp-shuffle phase 1, smem phase 2 =======================
__global__ void scan_kernel() {
    __shared__ int wsum[32];
    __shared__ int sm2[128];
    __shared__ int isLast;
    int t = threadIdx.x, lane = t & 31, wrp = t >> 5;
    int idx = blockIdx.x * 1024 + t;
    int d = (idx < N_NODES) ? g_deg[idx] : 0;
    int v = d;
    #pragma unroll
    for (int off = 1; off < 32; off <<= 1) {
        int u = __shfl_up_sync(0xffffffffu, v, off);
        if (lane >= off) v += u;
    }
    if (lane == 31) wsum[wrp] = v;
    __syncthreads();
    if (wrp == 0) {
        int s = wsum[lane];
        #pragma unroll
        for (int off = 1; off < 32; off <<= 1) {
            int u = __shfl_up_sync(0xffffffffu, s, off);
            if (lane >= off) s += u;
        }
        wsum[lane] = s;
    }
    __syncthreads();
    int incl = ((wrp > 0) ? wsum[wrp - 1] : 0) + v;
    if (idx < N_NODES) g_rowptr[idx] = incl - d;
    if (t == 1023) g_bsum[blockIdx.x] = incl;
    __threadfence();
    if (t == 0) {
        int done = atomicAdd(&g_scan_ctr, 1);
        isLast = (done == (int)gridDim.x - 1);
    }
    __syncthreads();
    if (!isLast) return;
    int nb = gridDim.x;
    int bv = (t < nb) ? ((volatile int*)g_bsum)[t] : 0;
    if (t < 128) sm2[t] = bv;
    __syncthreads();
    #pragma unroll
    for (int off = 1; off < 128; off <<= 1) {
        int u = (t >= off && t < 128) ? sm2[t - off] : 0;
        __syncthreads();
        if (t < 128) sm2[t] += u;
        __syncthreads();
    }
    if (t < nb) g_boff[t] = sm2[t] - bv;
    if (t == (N_NODES >> 10)) g_rowptr[N_NODES] = N_EDGES - (sm2[t] - bv);
}

// fill: position via atomicSub on deg (no cursor array; deg drained to 0)
__global__ void fill_kernel(const int* __restrict__ ei) {
    int e = blockIdx.x * blockDim.x + threadIdx.x;
    if (e < N_EDGES) {
        int src = ei[e];
        int dst = ei[N_EDGES + e];
        int pos = rowptr_at(dst) + atomicSub(&g_deg[dst], 1) - 1;
        g_csrsrc[pos] = src;
    }
}

// ======================= layer-1 aggregation (index-batched) -> fp16 hi/lo, K pad 32
__global__ void agg0_kernel(const float* __restrict__ x) {
    int w = (blockIdx.x * blockDim.x + threadIdx.x) >> 5;
    int lane = threadIdx.x & 31;
    if (w >= N_NODES) return;
    float acc = (lane < IN_F) ? x[w * IN_F + lane] : 0.f;
    int s0 = rowptr_at(w), s1 = rowptr_at(w + 1);
    for (int e = s0; e < s1; ) {
        int cnt = s1 - e; if (cnt > 8) cnt = 8;
        int idx[8];
        #pragma unroll
        for (int j = 0; j < 8; j++) idx[j] = (j < cnt) ? g_csrsrc[e + j] : 0;
        float v[8];
        #pragma unroll
        for (int j = 0; j < 8; j++)
            v[j] = (j < cnt && lane < IN_F) ? x[idx[j] * IN_F + lane] : 0.f;
        #pragma unroll
        for (int j = 0; j < 8; j++) acc += v[j];
        e += cnt;
    }
    __half h, l;
    fp16_split(acc, h, l);
    g_agg0_h[w * 32 + lane] = h;
    g_agg0_l[w * 32 + lane] = l;
}

// ======================= layer-2 aggregation: warp per (node, branch), fp16 z1 gather
__global__ void agg1_kernel() {
    int br = blockIdx.y;
    const uint2* Z = (const uint2*)(br ? g_z1t : g_z1s);
    int w = (blockIdx.x * blockDim.x + threadIdx.x) >> 5;
    int lane = threadIdx.x & 31;
    if (w >= N_NODES) return;
    float4 acc;
    {
        uint2 z = Z[(size_t)w * 32 + lane];
        float2 a = __half22float2(*(__half2*)&z.x);
        float2 b = __half22float2(*(__half2*)&z.y);
        acc = make_float4(a.x, a.y, b.x, b.y);
    }
    int s0 = rowptr_at(w), s1 = rowptr_at(w + 1);
    for (int e = s0; e < s1; ) {
        int cnt = s1 - e; if (cnt > 8) cnt = 8;
        int idx[8];
        #pragma unroll
        for (int j = 0; j < 8; j++) idx[j] = (j < cnt) ? g_csrsrc[e + j] : 0;
        uint2 v[8];
        #pragma unroll
        for (int j = 0; j < 8; j++)
            v[j] = (j < cnt) ? Z[(size_t)idx[j] * 32 + lane] : make_uint2(0u, 0u);
        #pragma unroll
        for (int j = 0; j < 8; j++) {
            float2 a = __half22float2(*(__half2*)&v[j].x);
            float2 b = __half22float2(*(__half2*)&v[j].y);
            acc.x += a.x; acc.y += a.y; acc.z += b.x; acc.w += b.y;
        }
        e += cnt;
    }
    __half2 p01 = __floats2half2_rn(acc.x, acc.y);
    __half2 p23 = __floats2half2_rn(acc.z, acc.w);
    __half* dst = br ? g_agg1t : g_agg1s;
    uint32_t* o = (uint32_t*)(dst + (size_t)w * 128 + lane * 4);
    o[0] = *(uint32_t*)&p01;
    o[1] = *(uint32_t*)&p23;
}

// ======================= W chunk loader: 64-col chunk, XOR-swizzled, pitch 64 halfs
__device__ __forceinline__ void load_w_chunk(
    __half* WH, __half* WL,
    const __half* __restrict__ Wh, const __half* __restrict__ Wl,
    int rows, int KS, int kk, int tid)
{
    for (int i = tid; i < rows * 8; i += 256) {
        int r = i >> 3, g = i & 7;
        int col = kk * 64 + g * 8;
        float4 vh = make_float4(0.f, 0.f, 0.f, 0.f), vl = vh;
        if (col < KS) {
            vh = *(const float4*)(Wh + r * KS + col);
            vl = *(const float4*)(Wl + r * KS + col);
        }
        int dst = r * 64 + ((g ^ (r & 7)) << 3);
        *(float4*)(WH + dst) = vh;
        *(float4*)(WL + dst) = vl;
    }
}

// ======================= fused 2-layer MLP, M-tile 64, 3 CTA/SM =======================
// ASPLIT=1 (layer 1, K1=32): A hi in granules 0-3 of AS, A lo packed in granules 8-11 -> 3 MMAs.
// ASPLIT=0 (layer 2, K1=128): A single fp16 -> 2 MMAs. pass2 both: H fp16, W2 split -> 2 MMAs.
template<int K1, int NT2, int ASPLIT>
__global__ __launch_bounds__(256, 3) void mlp_kernel(
    const float* __restrict__ B1a, const float* __restrict__ B1b,
    const float* __restrict__ B2a, const float* __restrict__ B2b)
{
    constexpr int NOUT2 = NT2 * 32;
    constexpr int GA = K1 / 8;
    constexpr int KCH1 = (K1 + 63) / 64;
    constexpr int KS1 = K1 / 16;
    extern __shared__ char smraw[];
    __half* AS = (__half*)smraw;          // 64x128 halfs (16 KB)
    __half* WH = AS + 64 * 128;           // 128x64 halfs
    __half* WL = WH + 128 * 64;

    int tid = threadIdx.x, lane = tid & 31, wid = tid >> 5;
    int warpM = wid & 1, warpN = wid >> 1;
    int by = blockIdx.y;
    int row0 = blockIdx.x * 64;
    int lg = lane >> 2, lt = lane & 3;

    int l1 = (K1 == 32) ? 0 : 2;
    const __half* Ag  = (K1 == 32) ? g_agg0_h : (by ? g_agg1t : g_agg1s);
    const __half* Agl = g_agg0_l;    // only used when ASPLIT
    const __half* W1h = g_pwh[by][l1];
    const __half* W1l = g_pwl[by][l1];
    const __half* W2h = g_pwh[by][l1 + 1];
    const __half* W2l = g_pwl[by][l1 + 1];
    const float* B1 = by ? B1b : B1a;
    const float* B2 = by ? B2b : B2a;

    // ---- A tile load: XOR swizzle, pitch 128 halfs; lo packed at +64 cols when ASPLIT ----
    for (int i = tid; i < 64 * GA; i += 256) {
        int r = i / GA, g = i % GA;
        int col = g * 8;
        int gr = row0 + r;
        float4 v = make_float4(0.f, 0.f, 0.f, 0.f);
        if (gr < N_NODES) v = *(const float4*)(Ag + (size_t)gr * K1 + col);
        int dst = r * 128 + ((g ^ (r & 7)) << 3);
        *(float4*)(AS + dst) = v;
        if (ASPLIT) {
            float4 vl = make_float4(0.f, 0.f, 0.f, 0.f);
            if (gr < N_NODES) vl = *(const float4*)(Agl + (size_t)gr * K1 + col);
            *(float4*)(AS + dst + 64) = vl;   // granule g+8 (bit3 clear in xA)
        }
    }
    load_w_chunk(WH, WL, W1h, W1l, 128, K1, 0, tid);
    __syncthreads();

    int a_row = lane & 15;
    int xA = lane & 7;
    int g0A = lane >> 4;
    int b_row = (lane & 7) + ((lane >> 4) & 1) * 8;
    int xW = b_row & 7;
    int g0W = (lane >> 3) & 1;

    uint32_t uAS = smem_u32(AS);
    uint32_t uWH = smem_u32(WH), uWL = smem_u32(WL);

    uint32_t aRB[2];
    #pragma unroll
    for (int tm = 0; tm < 2; tm++) {
        int R = warpM * 32 + tm * 16;
        aRB[tm] = uAS + (R + a_row) * 256;
    }

    // ---- pass 1: 64 x 128, warp tile 32 x 32 ----
    float acc[2][4][4];
    #pragma unroll
    for (int tm = 0; tm < 2; tm++)
        #pragma unroll
        for (int tn = 0; tn < 4; tn++)
            #pragma unroll
            for (int q = 0; q < 4; q++) acc[tm][tn][q] = 0.f;

    {
        uint32_t wRB_H[2], wRB_L[2];
        #pragma unroll
        for (int pp = 0; pp < 2; pp++) {
            int N0 = warpN * 32 + pp * 16;
            wRB_H[pp] = uWH + (N0 + b_row) * 128;
            wRB_L[pp] = uWL + (N0 + b_row) * 128;
        }
        constexpr int NKS = (KCH1 == 1) ? KS1 : 4;
        #pragma unroll
        for (int kk = 0; kk < KCH1; kk++) {
            if (kk > 0) {
                __syncthreads();
                load_w_chunk(WH, WL, W1h, W1l, 128, K1, kk, tid);
                __syncthreads();
            }
            #pragma unroll
            for (int ks = 0; ks < NKS; ks++) {
                int gs = kk * 4 + ks;
                uint32_t ao = (uint32_t)(((gs * 2 + g0A) ^ xA) << 4);
                uint32_t wo = (uint32_t)(((ks * 2 + g0W) ^ xW) << 4);
                uint32_t a[2][4], al[2][4];
                #pragma unroll
                for (int tm = 0; tm < 2; tm++) {
                    LDSM4(a[tm][0], a[tm][1], a[tm][2], a[tm][3], aRB[tm] + ao);
                    if (ASPLIT)
                        LDSM4(al[tm][0], al[tm][1], al[tm][2], al[tm][3], aRB[tm] + ao + 128);
                }
                #pragma unroll
                for (int pp = 0; pp < 2; pp++) {
                    uint32_t bh[4], bl[4];
                    LDSM4(bh[0], bh[1], bh[2], bh[3], wRB_H[pp] + wo);
                    LDSM4(bl[0], bl[1], bl[2], bl[3], wRB_L[pp] + wo);
                    #pragma unroll
                    for (int hf = 0; hf < 2; hf++) {
                        int tn = pp * 2 + hf;
                        #pragma unroll
                        for (int tm = 0; tm < 2; tm++) {
                            mma16816(acc[tm][tn], a[tm], bh + 2 * hf);
                            mma16816(acc[tm][tn], a[tm], bl + 2 * hf);
                            if (ASPLIT)
                                mma16816(acc[tm][tn], al[tm], bh + 2 * hf);
                        }
                    }
                }
            }
        }
    }
    __syncthreads();

    // ---- stage H = relu(acc + b1) -> AS (swizzled, fp16 single) ----
    #pragma unroll
    for (int tm = 0; tm < 2; tm++) {
        int m = warpM * 32 + tm * 16 + lg;
        #pragma unroll
        for (int tn = 0; tn < 4; tn++) {
            int n = warpN * 32 + tn * 8 + lt * 2;
            float2 bv = *(const float2*)(B1 + n);
            float v0 = fmaxf(acc[tm][tn][0] + bv.x, 0.f);
            float v1 = fmaxf(acc[tm][tn][1] + bv.y, 0.f);
            float v2 = fmaxf(acc[tm][tn][2] + bv.x, 0.f);
            float v3 = fmaxf(acc[tm][tn][3] + bv.y, 0.f);
            int off0 = m * 128 + (((n >> 3) ^ (m & 7)) << 3) + (n & 7);
            __half2 p0 = __floats2half2_rn(v0, v1);
            *(uint32_t*)(AS + off0) = *(uint32_t*)&p0;
            int off1 = (m + 8) * 128 + (((n >> 3) ^ (m & 7)) << 3) + (n & 7);
            __half2 p1 = __floats2half2_rn(v2, v3);
            *(uint32_t*)(AS + off1) = *(uint32_t*)&p1;
        }
    }
    load_w_chunk(WH, WL, W2h, W2l, NOUT2, 128, 0, tid);
    __syncthreads();

    // ---- pass 2: 64 x NOUT2, K = 128 ----
    float acc2[2][NT2][4];
    #pragma unroll
    for (int tm = 0; tm < 2; tm++)
        #pragma unroll
        for (int tn = 0; tn < NT2; tn++)
            #pragma unroll
            for (int q = 0; q < 4; q++) acc2[tm][tn][q] = 0.f;

    {
        uint32_t wRB_H[NT2 / 2], wRB_L[NT2 / 2];
        #pragma unroll
        for (int pp = 0; pp < NT2 / 2; pp++) {
            int N0 = warpN * (NOUT2 / 4) + pp * 16;
            wRB_H[pp] = uWH + (N0 + b_row) * 128;
            wRB_L[pp] = uWL + (N0 + b_row) * 128;
        }
        #pragma unroll
        for (int kk = 0; kk < 2; kk++) {
            if (kk > 0) {
                __syncthreads();
                load_w_chunk(WH, WL, W2h, W2l, NOUT2, 128, 1, tid);
                __syncthreads();
            }
            #pragma unroll
            for (int ks = 0; ks < 4; ks++) {
                int gs = kk * 4 + ks;
                uint32_t ao = (uint32_t)(((gs * 2 + g0A) ^ xA) << 4);
                uint32_t wo = (uint32_t)(((ks * 2 + g0W) ^ xW) << 4);
                uint32_t a[2][4];
                #pragma unroll
                for (int tm = 0; tm < 2; tm++)
                    LDSM4(a[tm][0], a[tm][1], a[tm][2], a[tm][3], aRB[tm] + ao);
                #pragma unroll
                for (int pp = 0; pp < NT2 / 2; pp++) {
                    uint32_t bh[4], bl[4];
                    LDSM4(bh[0], bh[1], bh[2], bh[3], wRB_H[pp] + wo);
                    LDSM4(bl[0], bl[1], bl[2], bl[3], wRB_L[pp] + wo);
                    #pragma unroll
                    for (int hf = 0; hf < 2; hf++) {
                        int tn = pp * 2 + hf;
                        #pragma unroll
                        for (int tm = 0; tm < 2; tm++) {
                            mma16816(acc2[tm][tn], a[tm], bh + 2 * hf);
                            mma16816(acc2[tm][tn], a[tm], bl + 2 * hf);
                        }
                    }
                }
            }
        }
    }

    // ---- epilogue: Z + b2 -> global (fp16 z1 for layer 1, fp32 z2 for layer 2) ----
    #pragma unroll
    for (int tm = 0; tm < 2; tm++) {
        int m = warpM * 32 + tm * 16 + lg;
        #pragma unroll
        for (int tn = 0; tn < NT2; tn++) {
            int n = warpN * (NOUT2 / 4) + tn * 8 + lt * 2;
            float2 bv = *(const float2*)(B2 + n);
            float o0x = acc2[tm][tn][0] + bv.x, o0y = acc2[tm][tn][1] + bv.y;
            float o1x = acc2[tm][tn][2] + bv.x, o1y = acc2[tm][tn][3] + bv.y;
            int g0 = row0 + m, g1 = row0 + m + 8;
            if (K1 == 32) {
                __half* z1 = by ? g_z1t : g_z1s;
                if (g0 < N_NODES) {
                    __half2 p = __floats2half2_rn(o0x, o0y);
                    *(uint32_t*)(z1 + (size_t)g0 * NOUT2 + n) = *(uint32_t*)&p;
                }
                if (g1 < N_NODES) {
                    __half2 p = __floats2half2_rn(o1x, o1y);
                    *(uint32_t*)(z1 + (size_t)g1 * NOUT2 + n) = *(uint32_t*)&p;
                }
            } else {
                float* z2 = by ? g_z2t : g_z2s;
                if (g0 < N_NODES) {
                    float2 o; o.x = o0x; o.y = o0y;
                    *(float2*)(z2 + (size_t)g0 * NOUT2 + n) = o;
                }
                if (g1 < N_NODES) {
                    float2 o; o.x = o1x; o.y = o1y;
                    *(float2*)(z2 + (size_t)g1 * NOUT2 + n) = o;
                }
            }
        }
    }
}

// ======================= per-graph 9x9 gram: 4 graphs per block =======================
__global__ void final_kernel(float* __restrict__ out) {
    __shared__ float zs[4][9 * 64];
    __shared__ float zt[4][9 * 64];
    int g0 = blockIdx.x * 4;
    int tid = threadIdx.x;
    const float4* ps = (const float4*)(g_z2s + (size_t)g0 * 9 * 64);
    const float4* pt = (const float4*)(g_z2t + (size_t)g0 * 9 * 64);
    for (int i = tid; i < 576; i += 512) {
        ((float4*)zs)[i] = ps[i];
        ((float4*)zt)[i] = pt[i];
    }
    __syncthreads();
    int gg = tid >> 7, t = tid & 127;
    if (t < 81) {
        int i = t / 9, j = t % 9;
        float acc = 0.f;
        #pragma unroll
        for (int k = 0; k < 64; k++) acc += zs[gg][i * 64 + k] * zt[gg][j * 64 + k];
        out[((g0 + gg) * 9 + i) * 9 + j] = acc;
    }
}

// ======================= launch =======================
extern "C" void kernel_launch(void* const* d_in, const int* in_sizes, int n_in,
                              void* d_out, int out_size) {
    const float* x  = (const float*)d_in[0];
    const int*   ei = (const int*)d_in[1];
    const float* B[2][4] = {
        { (const float*)d_in[3],  (const float*)d_in[5],  (const float*)d_in[7],  (const float*)d_in[9]  },
        { (const float*)d_in[11], (const float*)d_in[13], (const float*)d_in[15], (const float*)d_in[17] }
    };
    float* out = (float*)d_out;

    const int SMEM = (64 * 128 + 2 * 128 * 64) * 2;   // 49152 B -> 3 CTA/SM
    cudaFuncSetAttribute(mlp_kernel<32, 4, 1>,  cudaFuncAttributeMaxDynamicSharedMemorySize, SMEM);
    cudaFuncSetAttribute(mlp_kernel<128, 2, 0>, cudaFuncAttributeMaxDynamicSharedMemorySize, SMEM);

    const int GEMM_BLOCKS = (N_NODES + 63) / 64;         // 1407
    const int WARP_BLOCKS = (N_NODES * 32 + 255) / 256;
    const int SCAN_BLOCKS = (N_NODES + 1023) / 1024;     // 88

    // zero deg via memset node (capture-legal, full BW); no cursor array anymore
    void* p_deg = nullptr;
    cudaGetSymbolAddress(&p_deg, g_deg);
    cudaMemsetAsync(p_deg, 0, N_NODES * sizeof(int));

    // fused histogram + weight prep (concurrent independent work, one launch)
    hist_prep_kernel<<<HIST_BLOCKS + PREP_BLOCKS, 256>>>(ei,
        (const float*)d_in[2],  (const float*)d_in[4],  (const float*)d_in[6],  (const float*)d_in[8],
        (const float*)d_in[10], (const float*)d_in[12], (const float*)d_in[14], (const float*)d_in[16]);

    scan_kernel<<<SCAN_BLOCKS, 1024>>>();
    fill_kernel<<<(N_EDGES + 255) / 256, 256>>>(ei);

    agg0_kernel<<<WARP_BLOCKS, 256>>>(x);

    // GIN layer 1 (fused MLP, GEMM1 exact 3-term), both branches in one launch
    mlp_kernel<32, 4, 1><<<dim3(GEMM_BLOCKS, 2), 256, SMEM>>>(B[0][0], B[1][0], B[0][1], B[1][1]);

    // layer 2 aggregation: warp per (node, branch), fp16 gather
    agg1_kernel<<<dim3(WARP_BLOCKS, 2), 256>>>();

    // GIN layer 2 (fused MLP), both branches in one launch
    mlp_kernel<128, 2, 0><<<dim3(GEMM_BLOCKS, 2), 256, SMEM>>>(B[0][2], B[1][2], B[0][3], B[1][3]);

    final_kernel<<<(N_GRAPH + 3) / 4, 512>>>(out);
}